// round 1
// baseline (speedup 1.0000x reference)
#include <cuda_runtime.h>
#include <math.h>

#define BB 4
#define SS 2048
#define DD 768
#define HH 8
#define DHH 96
#define HID 3072
#define BS (BB*SS)          // 8192
#define SCALE_ATTN 0.1020620726159658f  // 1/sqrt(96)

// ---------------- scratch (device globals; no allocation) ----------------
__device__ float g_xn  [(size_t)BS * DD];        // LN1 out
__device__ float g_qkv [(size_t)BS * 3 * DD];    // qkv (rope applied in-place)
__device__ float g_attn[(size_t)BS * DD];        // attention out [b,s,h,dh]
__device__ float g_x1  [(size_t)BS * DD];        // src + proj(attn)
__device__ float g_y   [(size_t)BS * DD];        // LN2 out
__device__ float g_h   [(size_t)BS * HID];       // fc1+gelu out

// ---------------- LayerNorm: one block per row, 256 threads ----------------
__global__ __launch_bounds__(256) void ln_kernel(const float* __restrict__ x,
                                                 const float* __restrict__ g,
                                                 const float* __restrict__ b,
                                                 float* __restrict__ out) {
    int row = blockIdx.x;
    int t = threadIdx.x;
    const float* xr = x + (size_t)row * DD;
    float v0 = xr[t], v1 = xr[t + 256], v2 = xr[t + 512];
    float s  = v0 + v1 + v2;
    float ss = v0*v0 + v1*v1 + v2*v2;
    #pragma unroll
    for (int o = 16; o > 0; o >>= 1) {
        s  += __shfl_xor_sync(0xffffffffu, s,  o);
        ss += __shfl_xor_sync(0xffffffffu, ss, o);
    }
    __shared__ float rs[8], rss[8];
    if ((t & 31) == 0) { rs[t >> 5] = s; rss[t >> 5] = ss; }
    __syncthreads();
    float S1 = 0.f, S2 = 0.f;
    #pragma unroll
    for (int i = 0; i < 8; i++) { S1 += rs[i]; S2 += rss[i]; }
    float mean = S1 * (1.0f / DD);
    float var  = S2 * (1.0f / DD) - mean * mean;
    float rstd = rsqrtf(var + 1e-6f);
    float* orow = out + (size_t)row * DD;
    orow[t      ] = (v0 - mean) * rstd * g[t      ] + b[t      ];
    orow[t + 256] = (v1 - mean) * rstd * g[t + 256] + b[t + 256];
    orow[t + 512] = (v2 - mean) * rstd * g[t + 512] + b[t + 512];
}

// ---------------- Generic fp32 GEMM: C = A[MxK] @ W[KxN] + bias, epilogue ----
// mode 0: bias only; mode 1: bias + exact GELU; mode 2: bias + residual add
__global__ __launch_bounds__(256) void gemm_kernel(const float* __restrict__ A,
                                                   const float* __restrict__ W,
                                                   const float* __restrict__ bias,
                                                   const float* __restrict__ res,
                                                   float* __restrict__ C,
                                                   int M, int N, int K, int mode) {
    __shared__ float As[64][16];
    __shared__ float Ws[16][64];
    int tid = threadIdx.x;
    int tx = tid & 15, ty = tid >> 4;
    int m0 = blockIdx.y * 64, n0 = blockIdx.x * 64;
    int la_m = tid >> 2,  la_k = (tid & 3) << 2;   // A tile load: 64 rows x 16
    int lw_k = tid >> 4,  lw_n = (tid & 15) << 2;  // W tile load: 16 rows x 64

    float acc[4][4];
    #pragma unroll
    for (int i = 0; i < 4; i++)
        #pragma unroll
        for (int j = 0; j < 4; j++) acc[i][j] = 0.f;

    for (int kt = 0; kt < K; kt += 16) {
        float4 av = *(const float4*)&A[(size_t)(m0 + la_m) * K + kt + la_k];
        As[la_m][la_k    ] = av.x;
        As[la_m][la_k + 1] = av.y;
        As[la_m][la_k + 2] = av.z;
        As[la_m][la_k + 3] = av.w;
        *(float4*)&Ws[lw_k][lw_n] =
            *(const float4*)&W[(size_t)(kt + lw_k) * N + n0 + lw_n];
        __syncthreads();
        #pragma unroll
        for (int k = 0; k < 16; k++) {
            float a0 = As[ty * 4 + 0][k];
            float a1 = As[ty * 4 + 1][k];
            float a2 = As[ty * 4 + 2][k];
            float a3 = As[ty * 4 + 3][k];
            float4 w4 = *(const float4*)&Ws[k][tx * 4];
            acc[0][0] += a0 * w4.x; acc[0][1] += a0 * w4.y; acc[0][2] += a0 * w4.z; acc[0][3] += a0 * w4.w;
            acc[1][0] += a1 * w4.x; acc[1][1] += a1 * w4.y; acc[1][2] += a1 * w4.z; acc[1][3] += a1 * w4.w;
            acc[2][0] += a2 * w4.x; acc[2][1] += a2 * w4.y; acc[2][2] += a2 * w4.z; acc[2][3] += a2 * w4.w;
            acc[3][0] += a3 * w4.x; acc[3][1] += a3 * w4.y; acc[3][2] += a3 * w4.z; acc[3][3] += a3 * w4.w;
        }
        __syncthreads();
    }

    #pragma unroll
    for (int i = 0; i < 4; i++) {
        int mrow = m0 + ty * 4 + i;
        #pragma unroll
        for (int j = 0; j < 4; j++) {
            int n = n0 + tx * 4 + j;
            float c = acc[i][j] + bias[n];
            if (mode == 1) c = 0.5f * c * (1.0f + erff(c * 0.70710678118654752f));
            if (mode == 2) c += res[(size_t)mrow * N + n];
            C[(size_t)mrow * N + n] = c;
        }
    }
}

// ---------------- 3D RoPE applied in place to q and k in g_qkv --------------
__global__ __launch_bounds__(256) void rope_kernel(const float* __restrict__ coords) {
    int idx = blockIdx.x * blockDim.x + threadIdx.x;   // B*S*H*3*16 = 3145728
    int j    = idx & 15;
    int axis = (idx >> 4) % 3;
    int hd   = (idx / 48) & 7;
    int s    = (idx / 384) % SS;
    int b    =  idx / (384 * SS);
    float inv_freq = powf(10000.0f, -(float)j * (1.0f / 16.0f));
    float ang = coords[((size_t)(b * SS + s)) * 3 + axis] * inv_freq;
    float sn, cs;
    sincosf(ang, &sn, &cs);
    size_t base = (size_t)(b * SS + s) * (3 * DD) + hd * DHH + axis * 32 + j;
    float q1 = g_qkv[base], q2 = g_qkv[base + 16];
    g_qkv[base]      = q1 * cs - q2 * sn;
    g_qkv[base + 16] = q1 * sn + q2 * cs;
    float k1 = g_qkv[base + DD], k2 = g_qkv[base + DD + 16];
    g_qkv[base + DD]      = k1 * cs - k2 * sn;
    g_qkv[base + DD + 16] = k1 * sn + k2 * cs;
}

// ---------------- Causal flash attention: 64 q-rows / block, 64 threads -----
__global__ __launch_bounds__(64) void attn_kernel() {
    __shared__ float Ks[32][96];
    __shared__ float Vs[32][96];
    __shared__ float Ss[64][33];
    int t = threadIdx.x;
    int qtile = blockIdx.x;
    int b = blockIdx.y >> 3, h = blockIdx.y & 7;
    int qrow = qtile * 64 + t;
    const float* qkv = g_qkv + (size_t)b * SS * (3 * DD);

    float q[DHH], o[DHH];
    const float* qp = qkv + (size_t)qrow * (3 * DD) + h * DHH;
    #pragma unroll
    for (int d = 0; d < DHH; d++) { q[d] = qp[d]; o[d] = 0.f; }

    float m = -INFINITY, l = 0.f;
    int ntiles = (qtile * 64) / 32 + 2;   // covers k up to qtile*64+63

    for (int kt = 0; kt < ntiles; kt++) {
        int k0 = kt * 32;
        for (int i = t; i < 32 * 96; i += 64) {
            int r = i / 96, d = i % 96;
            const float* kp = qkv + (size_t)(k0 + r) * (3 * DD) + h * DHH;
            Ks[r][d] = kp[DD + d];
            Vs[r][d] = kp[2 * DD + d];
        }
        __syncthreads();

        float tmax = -INFINITY;
        #pragma unroll 4
        for (int j = 0; j < 32; j++) {
            float s0 = 0.f, s1 = 0.f, s2 = 0.f, s3 = 0.f;
            #pragma unroll
            for (int d = 0; d < DHH; d += 4) {
                float4 kk = *(const float4*)&Ks[j][d];
                s0 += q[d    ] * kk.x;
                s1 += q[d + 1] * kk.y;
                s2 += q[d + 2] * kk.z;
                s3 += q[d + 3] * kk.w;
            }
            float sc = ((s0 + s1) + (s2 + s3)) * SCALE_ATTN;
            if (k0 + j > qrow) sc = -INFINITY;
            Ss[t][j] = sc;
            tmax = fmaxf(tmax, sc);
        }
        float mnew = fmaxf(m, tmax);
        float alpha = expf(m - mnew);           // first tile: exp(-inf - finite)=0
        m = mnew;
        l *= alpha;
        #pragma unroll
        for (int d = 0; d < DHH; d++) o[d] *= alpha;

        #pragma unroll 2
        for (int j = 0; j < 32; j++) {
            float p = expf(Ss[t][j] - mnew);    // masked -> exp(-inf)=0
            l += p;
            #pragma unroll
            for (int d = 0; d < DHH; d += 4) {
                float4 vv = *(const float4*)&Vs[j][d];
                o[d    ] += p * vv.x;
                o[d + 1] += p * vv.y;
                o[d + 2] += p * vv.z;
                o[d + 3] += p * vv.w;
            }
        }
        __syncthreads();
    }

    float inv = 1.0f / l;
    float* op = g_attn + (size_t)(b * SS + qrow) * DD + h * DHH;
    #pragma unroll
    for (int d = 0; d < DHH; d++) op[d] = o[d] * inv;
}

// ---------------- launch ----------------------------------------------------
extern "C" void kernel_launch(void* const* d_in, const int* in_sizes, int n_in,
                              void* d_out, int out_size) {
    const float* src     = (const float*)d_in[0];
    const float* coords  = (const float*)d_in[1];
    // d_in[2] causal_mask: implied analytically
    const float* norm1_g = (const float*)d_in[3];
    const float* norm1_b = (const float*)d_in[4];
    const float* qkv_w   = (const float*)d_in[5];
    const float* qkv_b   = (const float*)d_in[6];
    const float* proj_w  = (const float*)d_in[7];
    const float* proj_b  = (const float*)d_in[8];
    const float* norm2_g = (const float*)d_in[9];
    const float* norm2_b = (const float*)d_in[10];
    const float* fc1_w   = (const float*)d_in[11];
    const float* fc1_b   = (const float*)d_in[12];
    const float* fc2_w   = (const float*)d_in[13];
    const float* fc2_b   = (const float*)d_in[14];
    float* out = (float*)d_out;

    float *xn, *qkvp, *attnp, *x1p, *yp, *hp;
    cudaGetSymbolAddress((void**)&xn,    g_xn);
    cudaGetSymbolAddress((void**)&qkvp,  g_qkv);
    cudaGetSymbolAddress((void**)&attnp, g_attn);
    cudaGetSymbolAddress((void**)&x1p,   g_x1);
    cudaGetSymbolAddress((void**)&yp,    g_y);
    cudaGetSymbolAddress((void**)&hp,    g_h);

    // 1. LN1
    ln_kernel<<<BS, 256>>>(src, norm1_g, norm1_b, xn);
    // 2. QKV GEMM: [8192,768] @ [768,2304]
    gemm_kernel<<<dim3((3 * DD) / 64, BS / 64), 256>>>(
        xn, qkv_w, qkv_b, nullptr, qkvp, BS, 3 * DD, DD, 0);
    // 3. RoPE in place on q,k
    rope_kernel<<<(BB * SS * HH * 3 * 16) / 256, 256>>>(coords);
    // 4. Causal attention
    attn_kernel<<<dim3(SS / 64, BB * HH), 64>>>();
    // 5. proj + residual(src) -> x1
    gemm_kernel<<<dim3(DD / 64, BS / 64), 256>>>(
        attnp, proj_w, proj_b, src, x1p, BS, DD, DD, 2);
    // 6. LN2
    ln_kernel<<<BS, 256>>>(x1p, norm2_g, norm2_b, yp);
    // 7. fc1 + GELU
    gemm_kernel<<<dim3(HID / 64, BS / 64), 256>>>(
        yp, fc1_w, fc1_b, nullptr, hp, BS, HID, DD, 1);
    // 8. fc2 + residual(x1) -> out
    gemm_kernel<<<dim3(DD / 64, BS / 64), 256>>>(
        hp, fc2_w, fc2_b, x1p, out, BS, DD, HID, 2);
}

// round 3
// speedup vs baseline: 1.7243x; 1.7243x over previous
#include <cuda_runtime.h>
#include <math.h>
#include <stdint.h>

#define BB 4
#define SS 2048
#define DD 768
#define HH 8
#define DHH 96
#define HID 3072
#define BS (BB*SS)          // 8192
#define SCALE_ATTN 0.1020620726159658f  // 1/sqrt(96)

// ---------------- scratch (device globals; no allocation) ----------------
__device__ float g_xn  [(size_t)BS * DD];        // LN1 out (tf32-rounded)
__device__ float g_qkv [(size_t)BS * 3 * DD];    // qkv (rope applied in-place)
__device__ float g_attn[(size_t)BS * DD];        // attention out (tf32-rounded)
__device__ float g_x1  [(size_t)BS * DD];        // src + proj(attn)
__device__ float g_y   [(size_t)BS * DD];        // LN2 out (tf32-rounded)
__device__ float g_h   [(size_t)BS * HID];       // fc1+gelu out (tf32-rounded)
// transposed weights Wt[N, K] (tf32-rounded)
__device__ float g_qkvwt[(size_t)(3*DD) * DD];
__device__ float g_projwt[(size_t)DD * DD];
__device__ float g_fc1wt [(size_t)HID * DD];
__device__ float g_fc2wt [(size_t)DD * HID];

// ---------------- helpers ---------------------------------------------------
__device__ __forceinline__ float tf32r(float x) {
    float y;
    asm("cvt.rna.tf32.f32 %0, %1;" : "=f"(y) : "f"(x));
    return y;
}
__device__ __forceinline__ void cp_async16(uint32_t dst, const void* src) {
    asm volatile("cp.async.cg.shared.global [%0], [%1], 16;" :: "r"(dst), "l"(src));
}
__device__ __forceinline__ void cp_commit() { asm volatile("cp.async.commit_group;" ::: "memory"); }
__device__ __forceinline__ uint32_t smem_u32(const void* p) {
    uint32_t a;
    asm("{ .reg .u64 t; cvta.to.shared.u64 t, %1; cvt.u32.u64 %0, t; }" : "=r"(a) : "l"(p));
    return a;
}
__device__ __forceinline__ void mma1688(float* c, const uint32_t* a, const uint32_t* b) {
    asm volatile(
        "mma.sync.aligned.m16n8k8.row.col.f32.tf32.tf32.f32 "
        "{%0,%1,%2,%3}, {%4,%5,%6,%7}, {%8,%9}, {%0,%1,%2,%3};"
        : "+f"(c[0]), "+f"(c[1]), "+f"(c[2]), "+f"(c[3])
        : "r"(a[0]), "r"(a[1]), "r"(a[2]), "r"(a[3]), "r"(b[0]), "r"(b[1]));
}

// ---------------- LayerNorm: one block per row, 256 threads ----------------
__global__ __launch_bounds__(256) void ln_kernel(const float* __restrict__ x,
                                                 const float* __restrict__ g,
                                                 const float* __restrict__ b,
                                                 float* __restrict__ out) {
    int row = blockIdx.x;
    int t = threadIdx.x;
    const float* xr = x + (size_t)row * DD;
    float v0 = xr[t], v1 = xr[t + 256], v2 = xr[t + 512];
    float s  = v0 + v1 + v2;
    float ss = v0*v0 + v1*v1 + v2*v2;
    #pragma unroll
    for (int o = 16; o > 0; o >>= 1) {
        s  += __shfl_xor_sync(0xffffffffu, s,  o);
        ss += __shfl_xor_sync(0xffffffffu, ss, o);
    }
    __shared__ float rs[8], rss[8];
    if ((t & 31) == 0) { rs[t >> 5] = s; rss[t >> 5] = ss; }
    __syncthreads();
    float S1 = 0.f, S2 = 0.f;
    #pragma unroll
    for (int i = 0; i < 8; i++) { S1 += rs[i]; S2 += rss[i]; }
    float mean = S1 * (1.0f / DD);
    float var  = S2 * (1.0f / DD) - mean * mean;
    float rstd = rsqrtf(var + 1e-6f);
    float* orow = out + (size_t)row * DD;
    orow[t      ] = tf32r((v0 - mean) * rstd * g[t      ] + b[t      ]);
    orow[t + 256] = tf32r((v1 - mean) * rstd * g[t + 256] + b[t + 256]);
    orow[t + 512] = tf32r((v2 - mean) * rstd * g[t + 512] + b[t + 512]);
}

// ---------------- weight transpose W[K,N] -> Wt[N,K], tf32-rounded ----------
__global__ __launch_bounds__(256) void transpose_kernel(const float* __restrict__ in,
                                                        float* __restrict__ out,
                                                        int K, int N) {
    __shared__ float tile[32][33];
    int x  = blockIdx.x * 32 + threadIdx.x;     // N index
    int y0 = blockIdx.y * 32;                   // K base
    #pragma unroll
    for (int i = threadIdx.y; i < 32; i += 8) {
        int y = y0 + i;
        if (x < N && y < K) tile[i][threadIdx.x] = in[(size_t)y * N + x];
    }
    __syncthreads();
    int ox  = y0 + threadIdx.x;                 // K index
    int oy0 = blockIdx.x * 32;                  // N base
    #pragma unroll
    for (int i = threadIdx.y; i < 32; i += 8) {
        int oy = oy0 + i;
        if (ox < K && oy < N) out[(size_t)oy * K + ox] = tf32r(tile[threadIdx.x][i]);
    }
}

// ---------------- mma.sync tf32 GEMM ----------------------------------------
// C[M,N] = A[M,K] @ Wt[N,K]^T + bias (+ GELU | + res)
// CTA tile 128x128, K chunk 32, 8 warps (4x2), warp tile 32x64.
// SMEM: 2 stages x (A 16KB + B 16KB), XOR swizzle col^( (row&7)<<2 ).
__global__ __launch_bounds__(256, 2) void gemm_tc(const float* __restrict__ A,
                                                  const float* __restrict__ Wt,
                                                  const float* __restrict__ bias,
                                                  const float* __restrict__ res,
                                                  float* __restrict__ C,
                                                  int M, int N, int K, int mode) {
    extern __shared__ char smem[];
    uint32_t sbase = smem_u32(smem);
    const int tid = threadIdx.x;
    const int m0 = blockIdx.y * 128, n0 = blockIdx.x * 128;

    // cp.async assignment: row r = tid>>1 (0..127), 4 chunks of 16B from (tid&1)*4
    const int r  = tid >> 1;
    const int cb = (tid & 1) * 4;
    const float* aP = A  + (size_t)(m0 + r) * K + cb * 4;
    const float* bP = Wt + (size_t)(n0 + r) * K + cb * 4;
    uint32_t swoff[4];
    #pragma unroll
    for (int j = 0; j < 4; j++)
        swoff[j] = (uint32_t)r * 128u + (uint32_t)(((cb + j) ^ (r & 7)) << 4);

    const int NC = K / 32;

    float acc[2][8][4];
    #pragma unroll
    for (int mt = 0; mt < 2; mt++)
        #pragma unroll
        for (int nt = 0; nt < 8; nt++)
            #pragma unroll
            for (int i = 0; i < 4; i++) acc[mt][nt][i] = 0.f;

    const int lane  = tid & 31, w = tid >> 5;
    const int lane4 = lane >> 2, lanem = lane & 3;
    const int wm = (w >> 1) * 32, wn = (w & 1) * 64;
    const uint32_t p = (uint32_t)(lane4 << 2);

    // prologue: stage 0
    {
        uint32_t sa = sbase, sb = sbase + 16384;
        #pragma unroll
        for (int j = 0; j < 4; j++) {
            cp_async16(sa + swoff[j], aP + j * 4);
            cp_async16(sb + swoff[j], bP + j * 4);
        }
        cp_commit();
    }

    for (int ch = 0; ch < NC; ch++) {
        if (ch + 1 < NC) {
            uint32_t na = sbase + (uint32_t)((ch + 1) & 1) * 32768u;
            uint32_t nb = na + 16384;
            const float* ap = aP + (size_t)(ch + 1) * 32;
            const float* bp = bP + (size_t)(ch + 1) * 32;
            #pragma unroll
            for (int j = 0; j < 4; j++) {
                cp_async16(na + swoff[j], ap + j * 4);
                cp_async16(nb + swoff[j], bp + j * 4);
            }
            cp_commit();
            asm volatile("cp.async.wait_group 1;" ::: "memory");
        } else {
            asm volatile("cp.async.wait_group 0;" ::: "memory");
        }
        __syncthreads();

        const uint32_t* As = (const uint32_t*)(smem + (size_t)(ch & 1) * 32768u);
        const uint32_t* Bs = As + 4096;

        // row bases (in uint32 elements)
        const uint32_t ra[2] = { (uint32_t)(wm + lane4) * 32u,
                                 (uint32_t)(wm + 16 + lane4) * 32u };
        uint32_t bn[8];
        #pragma unroll
        for (int nt = 0; nt < 8; nt++)
            bn[nt] = (uint32_t)(wn + nt * 8 + lane4) * 32u;

        #pragma unroll
        for (int ks = 0; ks < 4; ks++) {
            const uint32_t col0 = ((uint32_t)(ks * 8 + lanem)) ^ p;
            const uint32_t col1 = col0 ^ 4u;
            uint32_t afr[2][4];
            #pragma unroll
            for (int mt = 0; mt < 2; mt++) {
                afr[mt][0] = As[ra[mt] + col0];
                afr[mt][1] = As[ra[mt] + 256 + col0];   // +8 rows
                afr[mt][2] = As[ra[mt] + col1];
                afr[mt][3] = As[ra[mt] + 256 + col1];
            }
            uint32_t bfr[8][2];
            #pragma unroll
            for (int nt = 0; nt < 8; nt++) {
                bfr[nt][0] = Bs[bn[nt] + col0];
                bfr[nt][1] = Bs[bn[nt] + col1];
            }
            #pragma unroll
            for (int mt = 0; mt < 2; mt++)
                #pragma unroll
                for (int nt = 0; nt < 8; nt++)
                    mma1688(acc[mt][nt], afr[mt], bfr[nt]);
        }
        __syncthreads();
    }

    // epilogue: c0/c1 at (row=lane4, col=2*lanem,+1), c2/c3 at row+8
    #pragma unroll
    for (int mt = 0; mt < 2; mt++) {
        #pragma unroll
        for (int half = 0; half < 2; half++) {
            int m = m0 + wm + mt * 16 + lane4 + half * 8;
            float* crow = C + (size_t)m * N;
            const float* rrow = res + (size_t)m * N;
            #pragma unroll
            for (int nt = 0; nt < 8; nt++) {
                int n = n0 + wn + nt * 8 + 2 * lanem;
                float c0 = acc[mt][nt][half * 2    ] + bias[n];
                float c1 = acc[mt][nt][half * 2 + 1] + bias[n + 1];
                if (mode == 1) {
                    c0 = 0.5f * c0 * (1.0f + erff(c0 * 0.70710678118654752f));
                    c1 = 0.5f * c1 * (1.0f + erff(c1 * 0.70710678118654752f));
                    c0 = tf32r(c0); c1 = tf32r(c1);   // g_h feeds fc2 as A
                } else if (mode == 2) {
                    c0 += rrow[n]; c1 += rrow[n + 1];
                }
                crow[n]     = c0;
                crow[n + 1] = c1;
            }
        }
    }
}

// ---------------- 3D RoPE applied in place to q and k in g_qkv --------------
__global__ __launch_bounds__(256) void rope_kernel(const float* __restrict__ coords) {
    int idx = blockIdx.x * blockDim.x + threadIdx.x;   // B*S*H*3*16
    int j    = idx & 15;
    int axis = (idx >> 4) % 3;
    int hd   = (idx / 48) & 7;
    int s    = (idx / 384) % SS;
    int b    =  idx / (384 * SS);
    float inv_freq = powf(10000.0f, -(float)j * (1.0f / 16.0f));
    float ang = coords[((size_t)(b * SS + s)) * 3 + axis] * inv_freq;
    float sn, cs;
    sincosf(ang, &sn, &cs);
    size_t base = (size_t)(b * SS + s) * (3 * DD) + hd * DHH + axis * 32 + j;
    float q1 = g_qkv[base], q2 = g_qkv[base + 16];
    g_qkv[base]      = q1 * cs - q2 * sn;
    g_qkv[base + 16] = q1 * sn + q2 * cs;
    float k1 = g_qkv[base + DD], k2 = g_qkv[base + DD + 16];
    g_qkv[base + DD]      = k1 * cs - k2 * sn;
    g_qkv[base + DD + 16] = k1 * sn + k2 * cs;
}

// ---------------- Causal flash attention: 64 q-rows / block, 64 threads -----
__global__ __launch_bounds__(64) void attn_kernel() {
    __shared__ float Ks[32][96];
    __shared__ float Vs[32][96];
    __shared__ float Ss[64][33];
    int t = threadIdx.x;
    int qtile = blockIdx.x;
    int b = blockIdx.y >> 3, h = blockIdx.y & 7;
    int qrow = qtile * 64 + t;
    const float* qkv = g_qkv + (size_t)b * SS * (3 * DD);

    float q[DHH], o[DHH];
    const float* qp = qkv + (size_t)qrow * (3 * DD) + h * DHH;
    #pragma unroll
    for (int d = 0; d < DHH; d++) { q[d] = qp[d]; o[d] = 0.f; }

    float m = -INFINITY, l = 0.f;
    int ntiles = (qtile * 64) / 32 + 2;

    for (int kt = 0; kt < ntiles; kt++) {
        int k0 = kt * 32;
        for (int i = t; i < 32 * 96; i += 64) {
            int rr = i / 96, d = i % 96;
            const float* kp = qkv + (size_t)(k0 + rr) * (3 * DD) + h * DHH;
            Ks[rr][d] = kp[DD + d];
            Vs[rr][d] = kp[2 * DD + d];
        }
        __syncthreads();

        float tmax = -INFINITY;
        #pragma unroll 4
        for (int j = 0; j < 32; j++) {
            float s0 = 0.f, s1 = 0.f, s2 = 0.f, s3 = 0.f;
            #pragma unroll
            for (int d = 0; d < DHH; d += 4) {
                float4 kk = *(const float4*)&Ks[j][d];
                s0 += q[d    ] * kk.x;
                s1 += q[d + 1] * kk.y;
                s2 += q[d + 2] * kk.z;
                s3 += q[d + 3] * kk.w;
            }
            float sc = ((s0 + s1) + (s2 + s3)) * SCALE_ATTN;
            if (k0 + j > qrow) sc = -INFINITY;
            Ss[t][j] = sc;
            tmax = fmaxf(tmax, sc);
        }
        float mnew = fmaxf(m, tmax);
        float alpha = expf(m - mnew);
        m = mnew;
        l *= alpha;
        #pragma unroll
        for (int d = 0; d < DHH; d++) o[d] *= alpha;

        #pragma unroll 2
        for (int j = 0; j < 32; j++) {
            float pr = expf(Ss[t][j] - mnew);
            l += pr;
            #pragma unroll
            for (int d = 0; d < DHH; d += 4) {
                float4 vv = *(const float4*)&Vs[j][d];
                o[d    ] += pr * vv.x;
                o[d + 1] += pr * vv.y;
                o[d + 2] += pr * vv.z;
                o[d + 3] += pr * vv.w;
            }
        }
        __syncthreads();
    }

    float inv = 1.0f / l;
    float* op = g_attn + (size_t)(b * SS + qrow) * DD + h * DHH;
    #pragma unroll
    for (int d = 0; d < DHH; d++) op[d] = tf32r(o[d] * inv);  // A of proj GEMM
}

// ---------------- launch ----------------------------------------------------
extern "C" void kernel_launch(void* const* d_in, const int* in_sizes, int n_in,
                              void* d_out, int out_size) {
    const float* src     = (const float*)d_in[0];
    const float* coords  = (const float*)d_in[1];
    const float* norm1_g = (const float*)d_in[3];
    const float* norm1_b = (const float*)d_in[4];
    const float* qkv_w   = (const float*)d_in[5];
    const float* qkv_b   = (const float*)d_in[6];
    const float* proj_w  = (const float*)d_in[7];
    const float* proj_b  = (const float*)d_in[8];
    const float* norm2_g = (const float*)d_in[9];
    const float* norm2_b = (const float*)d_in[10];
    const float* fc1_w   = (const float*)d_in[11];
    const float* fc1_b   = (const float*)d_in[12];
    const float* fc2_w   = (const float*)d_in[13];
    const float* fc2_b   = (const float*)d_in[14];
    float* out = (float*)d_out;

    float *xn, *qkvp, *attnp, *x1p, *yp, *hp;
    float *qkvwt, *projwt, *fc1wt, *fc2wt;
    cudaGetSymbolAddress((void**)&xn,    g_xn);
    cudaGetSymbolAddress((void**)&qkvp,  g_qkv);
    cudaGetSymbolAddress((void**)&attnp, g_attn);
    cudaGetSymbolAddress((void**)&x1p,   g_x1);
    cudaGetSymbolAddress((void**)&yp,    g_y);
    cudaGetSymbolAddress((void**)&hp,    g_h);
    cudaGetSymbolAddress((void**)&qkvwt, g_qkvwt);
    cudaGetSymbolAddress((void**)&projwt,g_projwt);
    cudaGetSymbolAddress((void**)&fc1wt, g_fc1wt);
    cudaGetSymbolAddress((void**)&fc2wt, g_fc2wt);

    static bool attr_set = false;
    if (!attr_set) {
        cudaFuncSetAttribute(gemm_tc, cudaFuncAttributeMaxDynamicSharedMemorySize, 65536);
        attr_set = true;
    }

    // 0. transpose weights -> Wt[N,K] (tf32-rounded)
    transpose_kernel<<<dim3((3*DD)/32, DD/32), dim3(32,8)>>>(qkv_w, qkvwt, DD, 3*DD);
    transpose_kernel<<<dim3(DD/32, DD/32),     dim3(32,8)>>>(proj_w, projwt, DD, DD);
    transpose_kernel<<<dim3(HID/32, DD/32),    dim3(32,8)>>>(fc1_w, fc1wt, DD, HID);
    transpose_kernel<<<dim3(DD/32, HID/32),    dim3(32,8)>>>(fc2_w, fc2wt, HID, DD);

    // 1. LN1
    ln_kernel<<<BS, 256>>>(src, norm1_g, norm1_b, xn);
    // 2. QKV: [8192,768] @ [768,2304]
    gemm_tc<<<dim3((3*DD)/128, BS/128), 256, 65536>>>(
        xn, qkvwt, qkv_b, nullptr, qkvp, BS, 3*DD, DD, 0);
    // 3. RoPE in place on q,k
    rope_kernel<<<(BB * SS * HH * 3 * 16) / 256, 256>>>(coords);
    // 4. Causal attention
    attn_kernel<<<dim3(SS / 64, BB * HH), 64>>>();
    // 5. proj + residual(src) -> x1
    gemm_tc<<<dim3(DD/128, BS/128), 256, 65536>>>(
        attnp, projwt, proj_b, src, x1p, BS, DD, DD, 2);
    // 6. LN2
    ln_kernel<<<BS, 256>>>(x1p, norm2_g, norm2_b, yp);
    // 7. fc1 + GELU (output tf32-rounded in epilogue)
    gemm_tc<<<dim3(HID/128, BS/128), 256, 65536>>>(
        yp, fc1wt, fc1_b, nullptr, hp, BS, HID, DD, 1);
    // 8. fc2 + residual(x1) -> out
    gemm_tc<<<dim3(DD/128, BS/128), 256, 65536>>>(
        hp, fc2wt, fc2_b, x1p, out, BS, DD, HID, 2);
}

// round 4
// speedup vs baseline: 3.3087x; 1.9189x over previous
#include <cuda_runtime.h>
#include <math.h>
#include <stdint.h>

#define BB 4
#define SS 2048
#define DD 768
#define HH 8
#define DHH 96
#define HID 3072
#define BS (BB*SS)          // 8192
#define SCALE_ATTN 0.1020620726159658f  // 1/sqrt(96)

// ---------------- scratch (device globals; no allocation) ----------------
__device__ float g_xn  [(size_t)BS * DD];        // LN1 out (tf32-rounded)
__device__ float g_qkv [(size_t)BS * 3 * DD];    // qkv (rope applied in-place)
__device__ float g_attn[(size_t)BS * DD];        // attention out (tf32-rounded)
__device__ float g_x1  [(size_t)BS * DD];        // src + proj(attn)
__device__ float g_y   [(size_t)BS * DD];        // LN2 out (tf32-rounded)
__device__ float g_h   [(size_t)BS * HID];       // fc1+gelu out (tf32-rounded)
// transposed weights Wt[N, K] (tf32-rounded)
__device__ float g_qkvwt[(size_t)(3*DD) * DD];
__device__ float g_projwt[(size_t)DD * DD];
__device__ float g_fc1wt [(size_t)HID * DD];
__device__ float g_fc2wt [(size_t)DD * HID];

// ---------------- helpers ---------------------------------------------------
__device__ __forceinline__ float tf32r(float x) {
    float y;
    asm("cvt.rna.tf32.f32 %0, %1;" : "=f"(y) : "f"(x));
    return y;
}
__device__ __forceinline__ void cp_async16(uint32_t dst, const void* src) {
    asm volatile("cp.async.cg.shared.global [%0], [%1], 16;" :: "r"(dst), "l"(src));
}
__device__ __forceinline__ void cp_commit() { asm volatile("cp.async.commit_group;" ::: "memory"); }
__device__ __forceinline__ uint32_t smem_u32(const void* p) {
    uint32_t a;
    asm("{ .reg .u64 t; cvta.to.shared.u64 t, %1; cvt.u32.u64 %0, t; }" : "=r"(a) : "l"(p));
    return a;
}
__device__ __forceinline__ void mma1688(float* c, const uint32_t* a, const uint32_t* b) {
    asm volatile(
        "mma.sync.aligned.m16n8k8.row.col.f32.tf32.tf32.f32 "
        "{%0,%1,%2,%3}, {%4,%5,%6,%7}, {%8,%9}, {%0,%1,%2,%3};"
        : "+f"(c[0]), "+f"(c[1]), "+f"(c[2]), "+f"(c[3])
        : "r"(a[0]), "r"(a[1]), "r"(a[2]), "r"(a[3]), "r"(b[0]), "r"(b[1]));
}

// ---------------- LayerNorm: one block per row, 256 threads ----------------
__global__ __launch_bounds__(256) void ln_kernel(const float* __restrict__ x,
                                                 const float* __restrict__ g,
                                                 const float* __restrict__ b,
                                                 float* __restrict__ out) {
    int row = blockIdx.x;
    int t = threadIdx.x;
    const float* xr = x + (size_t)row * DD;
    float v0 = xr[t], v1 = xr[t + 256], v2 = xr[t + 512];
    float s  = v0 + v1 + v2;
    float ss = v0*v0 + v1*v1 + v2*v2;
    #pragma unroll
    for (int o = 16; o > 0; o >>= 1) {
        s  += __shfl_xor_sync(0xffffffffu, s,  o);
        ss += __shfl_xor_sync(0xffffffffu, ss, o);
    }
    __shared__ float rs[8], rss[8];
    if ((t & 31) == 0) { rs[t >> 5] = s; rss[t >> 5] = ss; }
    __syncthreads();
    float S1 = 0.f, S2 = 0.f;
    #pragma unroll
    for (int i = 0; i < 8; i++) { S1 += rs[i]; S2 += rss[i]; }
    float mean = S1 * (1.0f / DD);
    float var  = S2 * (1.0f / DD) - mean * mean;
    float rstd = rsqrtf(var + 1e-6f);
    float* orow = out + (size_t)row * DD;
    orow[t      ] = tf32r((v0 - mean) * rstd * g[t      ] + b[t      ]);
    orow[t + 256] = tf32r((v1 - mean) * rstd * g[t + 256] + b[t + 256]);
    orow[t + 512] = tf32r((v2 - mean) * rstd * g[t + 512] + b[t + 512]);
}

// ---------------- weight transpose W[K,N] -> Wt[N,K], tf32-rounded ----------
__global__ __launch_bounds__(256) void transpose_kernel(const float* __restrict__ in,
                                                        float* __restrict__ out,
                                                        int K, int N) {
    __shared__ float tile[32][33];
    int x  = blockIdx.x * 32 + threadIdx.x;
    int y0 = blockIdx.y * 32;
    #pragma unroll
    for (int i = threadIdx.y; i < 32; i += 8) {
        int y = y0 + i;
        if (x < N && y < K) tile[i][threadIdx.x] = in[(size_t)y * N + x];
    }
    __syncthreads();
    int ox  = y0 + threadIdx.x;
    int oy0 = blockIdx.x * 32;
    #pragma unroll
    for (int i = threadIdx.y; i < 32; i += 8) {
        int oy = oy0 + i;
        if (ox < K && oy < N) out[(size_t)oy * K + ox] = tf32r(tile[threadIdx.x][i]);
    }
}

// ---------------- mma.sync tf32 GEMM ----------------------------------------
__global__ __launch_bounds__(256, 2) void gemm_tc(const float* __restrict__ A,
                                                  const float* __restrict__ Wt,
                                                  const float* __restrict__ bias,
                                                  const float* __restrict__ res,
                                                  float* __restrict__ C,
                                                  int M, int N, int K, int mode) {
    extern __shared__ char smem[];
    uint32_t sbase = smem_u32(smem);
    const int tid = threadIdx.x;
    const int m0 = blockIdx.y * 128, n0 = blockIdx.x * 128;

    const int r  = tid >> 1;
    const int cb = (tid & 1) * 4;
    const float* aP = A  + (size_t)(m0 + r) * K + cb * 4;
    const float* bP = Wt + (size_t)(n0 + r) * K + cb * 4;
    uint32_t swoff[4];
    #pragma unroll
    for (int j = 0; j < 4; j++)
        swoff[j] = (uint32_t)r * 128u + (uint32_t)(((cb + j) ^ (r & 7)) << 4);

    const int NC = K / 32;

    float acc[2][8][4];
    #pragma unroll
    for (int mt = 0; mt < 2; mt++)
        #pragma unroll
        for (int nt = 0; nt < 8; nt++)
            #pragma unroll
            for (int i = 0; i < 4; i++) acc[mt][nt][i] = 0.f;

    const int lane  = tid & 31, w = tid >> 5;
    const int lane4 = lane >> 2, lanem = lane & 3;
    const int wm = (w >> 1) * 32, wn = (w & 1) * 64;
    const uint32_t p = (uint32_t)(lane4 << 2);

    {
        uint32_t sa = sbase, sb = sbase + 16384;
        #pragma unroll
        for (int j = 0; j < 4; j++) {
            cp_async16(sa + swoff[j], aP + j * 4);
            cp_async16(sb + swoff[j], bP + j * 4);
        }
        cp_commit();
    }

    for (int ch = 0; ch < NC; ch++) {
        if (ch + 1 < NC) {
            uint32_t na = sbase + (uint32_t)((ch + 1) & 1) * 32768u;
            uint32_t nb = na + 16384;
            const float* ap = aP + (size_t)(ch + 1) * 32;
            const float* bp = bP + (size_t)(ch + 1) * 32;
            #pragma unroll
            for (int j = 0; j < 4; j++) {
                cp_async16(na + swoff[j], ap + j * 4);
                cp_async16(nb + swoff[j], bp + j * 4);
            }
            cp_commit();
            asm volatile("cp.async.wait_group 1;" ::: "memory");
        } else {
            asm volatile("cp.async.wait_group 0;" ::: "memory");
        }
        __syncthreads();

        const uint32_t* As = (const uint32_t*)(smem + (size_t)(ch & 1) * 32768u);
        const uint32_t* Bs = As + 4096;

        const uint32_t ra[2] = { (uint32_t)(wm + lane4) * 32u,
                                 (uint32_t)(wm + 16 + lane4) * 32u };
        uint32_t bn[8];
        #pragma unroll
        for (int nt = 0; nt < 8; nt++)
            bn[nt] = (uint32_t)(wn + nt * 8 + lane4) * 32u;

        #pragma unroll
        for (int ks = 0; ks < 4; ks++) {
            const uint32_t col0 = ((uint32_t)(ks * 8 + lanem)) ^ p;
            const uint32_t col1 = col0 ^ 4u;
            uint32_t afr[2][4];
            #pragma unroll
            for (int mt = 0; mt < 2; mt++) {
                afr[mt][0] = As[ra[mt] + col0];
                afr[mt][1] = As[ra[mt] + 256 + col0];
                afr[mt][2] = As[ra[mt] + col1];
                afr[mt][3] = As[ra[mt] + 256 + col1];
            }
            uint32_t bfr[8][2];
            #pragma unroll
            for (int nt = 0; nt < 8; nt++) {
                bfr[nt][0] = Bs[bn[nt] + col0];
                bfr[nt][1] = Bs[bn[nt] + col1];
            }
            #pragma unroll
            for (int mt = 0; mt < 2; mt++)
                #pragma unroll
                for (int nt = 0; nt < 8; nt++)
                    mma1688(acc[mt][nt], afr[mt], bfr[nt]);
        }
        __syncthreads();
    }

    #pragma unroll
    for (int mt = 0; mt < 2; mt++) {
        #pragma unroll
        for (int half = 0; half < 2; half++) {
            int m = m0 + wm + mt * 16 + lane4 + half * 8;
            float* crow = C + (size_t)m * N;
            const float* rrow = res + (size_t)m * N;
            #pragma unroll
            for (int nt = 0; nt < 8; nt++) {
                int n = n0 + wn + nt * 8 + 2 * lanem;
                float c0 = acc[mt][nt][half * 2    ] + bias[n];
                float c1 = acc[mt][nt][half * 2 + 1] + bias[n + 1];
                if (mode == 1) {
                    c0 = 0.5f * c0 * (1.0f + erff(c0 * 0.70710678118654752f));
                    c1 = 0.5f * c1 * (1.0f + erff(c1 * 0.70710678118654752f));
                    c0 = tf32r(c0); c1 = tf32r(c1);
                } else if (mode == 2) {
                    c0 += rrow[n]; c1 += rrow[n + 1];
                }
                crow[n]     = c0;
                crow[n + 1] = c1;
            }
        }
    }
}

// ---------------- 3D RoPE: in place on q,k; scale+tf32-round q, round k -----
__global__ __launch_bounds__(256) void rope_kernel(const float* __restrict__ coords) {
    int idx = blockIdx.x * blockDim.x + threadIdx.x;
    int j    = idx & 15;
    int axis = (idx >> 4) % 3;
    int hd   = (idx / 48) & 7;
    int s    = (idx / 384) % SS;
    int b    =  idx / (384 * SS);
    float inv_freq = powf(10000.0f, -(float)j * (1.0f / 16.0f));
    float ang = coords[((size_t)(b * SS + s)) * 3 + axis] * inv_freq;
    float sn, cs;
    sincosf(ang, &sn, &cs);
    size_t base = (size_t)(b * SS + s) * (3 * DD) + hd * DHH + axis * 32 + j;
    float q1 = g_qkv[base], q2 = g_qkv[base + 16];
    g_qkv[base]      = tf32r(SCALE_ATTN * (q1 * cs - q2 * sn));
    g_qkv[base + 16] = tf32r(SCALE_ATTN * (q1 * sn + q2 * cs));
    float k1 = g_qkv[base + DD], k2 = g_qkv[base + DD + 16];
    g_qkv[base + DD]      = tf32r(k1 * cs - k2 * sn);
    g_qkv[base + DD + 16] = tf32r(k1 * sn + k2 * cs);
}

// ---------------- Tensor-core causal flash attention -----------------------
// 64 q-rows per block, 128 threads (4 warps x 16 rows). kv tiles of 64.
// smem: K region 3 chunks x [64][32] floats (also used to stage Q);
//       Vt region 2 chunks x [96][32] floats (V transposed, tf32-rounded).
__global__ __launch_bounds__(128) void attn_tc() {
    __shared__ float sm[12288];                 // 48 KB
    float* Vsm = sm + 6144;
    const int t = threadIdx.x, lane = t & 31, w = t >> 5;
    const int lane4 = lane >> 2, u = lane & 3;
    const int qt = blockIdx.x, bh = blockIdx.y;
    const int b = bh >> 3, h = bh & 7;
    const float* qkv = g_qkv + (size_t)b * SS * (3 * DD);
    const uint32_t sKb = smem_u32(sm);

    // cp.async pattern (shared by Q and K staging)
    uint32_t dsts[12]; int rws[12], dqs[12];
    #pragma unroll
    for (int it = 0; it < 12; it++) {
        int idx = t + 128 * it;
        int rr = idx / 24, dq = idx % 24;
        int chunk = dq >> 3;
        int unit = (dq & 7) ^ (rr & 7);
        dsts[it] = sKb + (uint32_t)(chunk * 8192 + rr * 128 + unit * 16);
        rws[it] = rr; dqs[it] = dq;
    }

    // ---- stage Q, load Q fragments to registers
    #pragma unroll
    for (int it = 0; it < 12; it++)
        cp_async16(dsts[it], qkv + (size_t)(qt * 64 + rws[it]) * (3 * DD) + h * DHH + dqs[it] * 4);
    cp_commit();
    asm volatile("cp.async.wait_group 0;" ::: "memory");
    __syncthreads();

    const uint32_t* Ku = (const uint32_t*)sm;
    uint32_t qa[12][4];
    #pragma unroll
    for (int ks = 0; ks < 12; ks++) {
        int chunk = ks >> 2, cu = (ks & 3) * 2;
        int c0 = u + ((cu ^ lane4) << 2);
        int c1 = u + (((cu + 1) ^ lane4) << 2);
        int base0 = chunk * 2048 + (w * 16 + lane4) * 32;
        qa[ks][0] = Ku[base0 + c0];
        qa[ks][1] = Ku[base0 + 256 + c0];
        qa[ks][2] = Ku[base0 + c1];
        qa[ks][3] = Ku[base0 + 256 + c1];
    }

    float oacc[12][4];
    #pragma unroll
    for (int nt = 0; nt < 12; nt++)
        #pragma unroll
        for (int i = 0; i < 4; i++) oacc[nt][i] = 0.f;
    float m0 = -INFINITY, m1 = -INFINITY, l0 = 0.f, l1 = 0.f;

    const int kvl = t & 63, dqb = t >> 6;
    const int vchunk = kvl >> 5, kvm = kvl & 31;
    const int vcbase = vchunk * 96 * 32;

    for (int kt = 0; kt <= qt; kt++) {
        __syncthreads();
        // K tile via cp.async
        #pragma unroll
        for (int it = 0; it < 12; it++)
            cp_async16(dsts[it], qkv + (size_t)(kt * 64 + rws[it]) * (3 * DD) + DD + h * DHH + dqs[it] * 4);
        cp_commit();
        // V tile: transpose + round into Vsm
        const float* vp = qkv + (size_t)(kt * 64 + kvl) * (3 * DD) + 2 * DD + h * DHH;
        #pragma unroll
        for (int it = 0; it < 12; it++) {
            int d0 = (dqb + 2 * it) * 4;
            float4 v = *(const float4*)(vp + d0);
            #pragma unroll
            for (int i = 0; i < 4; i++) {
                int d = d0 + i;
                int colf = (kvm & 3) + (((kvm >> 2) ^ (d & 7)) << 2);
                float val = (i == 0) ? v.x : (i == 1) ? v.y : (i == 2) ? v.z : v.w;
                Vsm[vcbase + d * 32 + colf] = tf32r(val);
            }
        }
        asm volatile("cp.async.wait_group 0;" ::: "memory");
        __syncthreads();

        // ---- S = Q K^T
        float sfr[8][4];
        #pragma unroll
        for (int nt = 0; nt < 8; nt++)
            #pragma unroll
            for (int i = 0; i < 4; i++) sfr[nt][i] = 0.f;
        #pragma unroll
        for (int ks = 0; ks < 12; ks++) {
            int chunk = ks >> 2, cu = (ks & 3) * 2;
            int c0 = u + ((cu ^ lane4) << 2);
            int c1 = u + (((cu + 1) ^ lane4) << 2);
            int cbk = chunk * 2048 + lane4 * 32;
            #pragma unroll
            for (int nt = 0; nt < 8; nt++) {
                uint32_t bb[2];
                bb[0] = Ku[cbk + nt * 256 + c0];
                bb[1] = Ku[cbk + nt * 256 + c1];
                mma1688(sfr[nt], qa[ks], bb);
            }
        }
        // ---- causal mask on diagonal tile
        if (kt == qt) {
            int r0 = w * 16 + lane4, r1 = r0 + 8;
            #pragma unroll
            for (int nt = 0; nt < 8; nt++) {
                int ca = nt * 8 + 2 * u, cbn = ca + 1;
                if (ca  > r0) sfr[nt][0] = -1e30f;
                if (cbn > r0) sfr[nt][1] = -1e30f;
                if (ca  > r1) sfr[nt][2] = -1e30f;
                if (cbn > r1) sfr[nt][3] = -1e30f;
            }
        }
        // ---- online softmax
        float mx0 = -INFINITY, mx1 = -INFINITY;
        #pragma unroll
        for (int nt = 0; nt < 8; nt++) {
            mx0 = fmaxf(mx0, fmaxf(sfr[nt][0], sfr[nt][1]));
            mx1 = fmaxf(mx1, fmaxf(sfr[nt][2], sfr[nt][3]));
        }
        mx0 = fmaxf(mx0, __shfl_xor_sync(0xffffffffu, mx0, 1));
        mx0 = fmaxf(mx0, __shfl_xor_sync(0xffffffffu, mx0, 2));
        mx1 = fmaxf(mx1, __shfl_xor_sync(0xffffffffu, mx1, 1));
        mx1 = fmaxf(mx1, __shfl_xor_sync(0xffffffffu, mx1, 2));
        float mn0 = fmaxf(m0, mx0), mn1 = fmaxf(m1, mx1);
        float al0 = __expf(m0 - mn0), al1 = __expf(m1 - mn1);
        m0 = mn0; m1 = mn1;
        l0 *= al0; l1 *= al1;
        #pragma unroll
        for (int nt = 0; nt < 12; nt++) {
            oacc[nt][0] *= al0; oacc[nt][1] *= al0;
            oacc[nt][2] *= al1; oacc[nt][3] *= al1;
        }
        #pragma unroll
        for (int nt = 0; nt < 8; nt++) {
            float p0 = __expf(sfr[nt][0] - mn0), p1 = __expf(sfr[nt][1] - mn0);
            float p2 = __expf(sfr[nt][2] - mn1), p3 = __expf(sfr[nt][3] - mn1);
            l0 += p0 + p1; l1 += p2 + p3;
            sfr[nt][0] = p0; sfr[nt][1] = p1; sfr[nt][2] = p2; sfr[nt][3] = p3;
        }
        // ---- O += P V  (a-frags gathered from c-frags via quad shuffles)
        const uint32_t* Vu = (const uint32_t*)Vsm;
        int src0 = (lane & ~3) | (u >> 1);
        int src1 = src0 + 2;
        #pragma unroll
        for (int k8 = 0; k8 < 8; k8++) {
            float P0 = sfr[k8][0], P1 = sfr[k8][1], P2 = sfr[k8][2], P3 = sfr[k8][3];
            float v00 = __shfl_sync(0xffffffffu, P0, src0);
            float v01 = __shfl_sync(0xffffffffu, P1, src0);
            float v10 = __shfl_sync(0xffffffffu, P2, src0);
            float v11 = __shfl_sync(0xffffffffu, P3, src0);
            float w00 = __shfl_sync(0xffffffffu, P0, src1);
            float w01 = __shfl_sync(0xffffffffu, P1, src1);
            float w10 = __shfl_sync(0xffffffffu, P2, src1);
            float w11 = __shfl_sync(0xffffffffu, P3, src1);
            uint32_t a[4];
            a[0] = __float_as_uint((u & 1) ? v01 : v00);
            a[1] = __float_as_uint((u & 1) ? v11 : v10);
            a[2] = __float_as_uint((u & 1) ? w01 : w00);
            a[3] = __float_as_uint((u & 1) ? w11 : w10);
            int chunk = k8 >> 2, cu = (k8 & 3) * 2;
            int c0 = u + ((cu ^ lane4) << 2);
            int c1 = u + (((cu + 1) ^ lane4) << 2);
            int cbv = chunk * 3072 + lane4 * 32;
            #pragma unroll
            for (int nt = 0; nt < 12; nt++) {
                uint32_t bb[2];
                bb[0] = Vu[cbv + nt * 256 + c0];
                bb[1] = Vu[cbv + nt * 256 + c1];
                mma1688(oacc[nt], a, bb);
            }
        }
    }

    // ---- finalize
    l0 += __shfl_xor_sync(0xffffffffu, l0, 1);
    l0 += __shfl_xor_sync(0xffffffffu, l0, 2);
    l1 += __shfl_xor_sync(0xffffffffu, l1, 1);
    l1 += __shfl_xor_sync(0xffffffffu, l1, 2);
    float i0 = 1.0f / l0, i1 = 1.0f / l1;
    int gr0 = qt * 64 + w * 16 + lane4, gr1 = gr0 + 8;
    float* o0 = g_attn + (size_t)(b * SS + gr0) * DD + h * DHH;
    float* o1 = g_attn + (size_t)(b * SS + gr1) * DD + h * DHH;
    #pragma unroll
    for (int nt = 0; nt < 12; nt++) {
        int c = nt * 8 + 2 * u;
        o0[c]     = tf32r(oacc[nt][0] * i0);
        o0[c + 1] = tf32r(oacc[nt][1] * i0);
        o1[c]     = tf32r(oacc[nt][2] * i1);
        o1[c + 1] = tf32r(oacc[nt][3] * i1);
    }
}

// ---------------- launch ----------------------------------------------------
extern "C" void kernel_launch(void* const* d_in, const int* in_sizes, int n_in,
                              void* d_out, int out_size) {
    const float* src     = (const float*)d_in[0];
    const float* coords  = (const float*)d_in[1];
    const float* norm1_g = (const float*)d_in[3];
    const float* norm1_b = (const float*)d_in[4];
    const float* qkv_w   = (const float*)d_in[5];
    const float* qkv_b   = (const float*)d_in[6];
    const float* proj_w  = (const float*)d_in[7];
    const float* proj_b  = (const float*)d_in[8];
    const float* norm2_g = (const float*)d_in[9];
    const float* norm2_b = (const float*)d_in[10];
    const float* fc1_w   = (const float*)d_in[11];
    const float* fc1_b   = (const float*)d_in[12];
    const float* fc2_w   = (const float*)d_in[13];
    const float* fc2_b   = (const float*)d_in[14];
    float* out = (float*)d_out;

    float *xn, *qkvp, *attnp, *x1p, *yp, *hp;
    float *qkvwt, *projwt, *fc1wt, *fc2wt;
    cudaGetSymbolAddress((void**)&xn,    g_xn);
    cudaGetSymbolAddress((void**)&qkvp,  g_qkv);
    cudaGetSymbolAddress((void**)&attnp, g_attn);
    cudaGetSymbolAddress((void**)&x1p,   g_x1);
    cudaGetSymbolAddress((void**)&yp,    g_y);
    cudaGetSymbolAddress((void**)&hp,    g_h);
    cudaGetSymbolAddress((void**)&qkvwt, g_qkvwt);
    cudaGetSymbolAddress((void**)&projwt,g_projwt);
    cudaGetSymbolAddress((void**)&fc1wt, g_fc1wt);
    cudaGetSymbolAddress((void**)&fc2wt, g_fc2wt);

    static bool attr_set = false;
    if (!attr_set) {
        cudaFuncSetAttribute(gemm_tc, cudaFuncAttributeMaxDynamicSharedMemorySize, 65536);
        attr_set = true;
    }

    // 0. transpose weights -> Wt[N,K] (tf32-rounded)
    transpose_kernel<<<dim3((3*DD)/32, DD/32), dim3(32,8)>>>(qkv_w, qkvwt, DD, 3*DD);
    transpose_kernel<<<dim3(DD/32, DD/32),     dim3(32,8)>>>(proj_w, projwt, DD, DD);
    transpose_kernel<<<dim3(HID/32, DD/32),    dim3(32,8)>>>(fc1_w, fc1wt, DD, HID);
    transpose_kernel<<<dim3(DD/32, HID/32),    dim3(32,8)>>>(fc2_w, fc2wt, HID, DD);

    // 1. LN1
    ln_kernel<<<BS, 256>>>(src, norm1_g, norm1_b, xn);
    // 2. QKV
    gemm_tc<<<dim3((3*DD)/128, BS/128), 256, 65536>>>(
        xn, qkvwt, qkv_b, nullptr, qkvp, BS, 3*DD, DD, 0);
    // 3. RoPE (scale+round q, round k)
    rope_kernel<<<(BB * SS * HH * 3 * 16) / 256, 256>>>(coords);
    // 4. Tensor-core causal attention
    attn_tc<<<dim3(SS / 64, BB * HH), 128>>>();
    // 5. proj + residual(src) -> x1
    gemm_tc<<<dim3(DD/128, BS/128), 256, 65536>>>(
        attnp, projwt, proj_b, src, x1p, BS, DD, DD, 2);
    // 6. LN2
    ln_kernel<<<BS, 256>>>(x1p, norm2_g, norm2_b, yp);
    // 7. fc1 + GELU
    gemm_tc<<<dim3(HID/128, BS/128), 256, 65536>>>(
        yp, fc1wt, fc1_b, nullptr, hp, BS, HID, DD, 1);
    // 8. fc2 + residual(x1) -> out
    gemm_tc<<<dim3(DD/128, BS/128), 256, 65536>>>(
        hp, fc2wt, fc2_b, x1p, out, BS, DD, HID, 2);
}

// round 5
// speedup vs baseline: 6.4666x; 1.9544x over previous
#include <cuda_runtime.h>
#include <cuda_fp16.h>
#include <math.h>
#include <stdint.h>

#define BB 4
#define SS 2048
#define DD 768
#define HH 8
#define DHH 96
#define HID 3072
#define BS (BB*SS)          // 8192
#define SCALE_ATTN 0.1020620726159658f  // 1/sqrt(96)

// ---------------- scratch (device globals; no allocation) ----------------
__device__ __half g_xn  [(size_t)BS * DD];        // LN1 out (fp16)
__device__ __half g_qkv [(size_t)BS * 3 * DD];    // qkv fp16 (rope in-place)
__device__ __half g_attn[(size_t)BS * DD];        // attention out fp16
__device__ float  g_x1  [(size_t)BS * DD];        // src + proj(attn), fp32 trunk
__device__ __half g_y   [(size_t)BS * DD];        // LN2 out fp16
__device__ __half g_h   [(size_t)BS * HID];       // fc1+gelu out fp16
// transposed weights Wt[N, K] fp16
__device__ __half g_qkvwt[(size_t)(3*DD) * DD];
__device__ __half g_projwt[(size_t)DD * DD];
__device__ __half g_fc1wt [(size_t)HID * DD];
__device__ __half g_fc2wt [(size_t)DD * HID];

// ---------------- helpers ---------------------------------------------------
__device__ __forceinline__ void cp_async16(uint32_t dst, const void* src) {
    asm volatile("cp.async.cg.shared.global [%0], [%1], 16;" :: "r"(dst), "l"(src));
}
__device__ __forceinline__ void cp_commit() { asm volatile("cp.async.commit_group;" ::: "memory"); }
__device__ __forceinline__ uint32_t smem_u32(const void* p) {
    uint32_t a;
    asm("{ .reg .u64 t; cvta.to.shared.u64 t, %1; cvt.u32.u64 %0, t; }" : "=r"(a) : "l"(p));
    return a;
}
__device__ __forceinline__ void ldm_x4(uint32_t* r, uint32_t addr) {
    asm volatile("ldmatrix.sync.aligned.m8n8.x4.shared.b16 {%0,%1,%2,%3}, [%4];"
        : "=r"(r[0]), "=r"(r[1]), "=r"(r[2]), "=r"(r[3]) : "r"(addr));
}
__device__ __forceinline__ void mma16816(float* c, const uint32_t* a, const uint32_t* b) {
    asm volatile(
        "mma.sync.aligned.m16n8k16.row.col.f32.f16.f16.f32 "
        "{%0,%1,%2,%3}, {%4,%5,%6,%7}, {%8,%9}, {%0,%1,%2,%3};"
        : "+f"(c[0]), "+f"(c[1]), "+f"(c[2]), "+f"(c[3])
        : "r"(a[0]), "r"(a[1]), "r"(a[2]), "r"(a[3]), "r"(b[0]), "r"(b[1]));
}

// ---------------- LayerNorm: one block per row, out fp16 --------------------
__global__ __launch_bounds__(256) void ln_kernel(const float* __restrict__ x,
                                                 const float* __restrict__ g,
                                                 const float* __restrict__ b,
                                                 __half* __restrict__ out) {
    int row = blockIdx.x;
    int t = threadIdx.x;
    const float* xr = x + (size_t)row * DD;
    float v0 = xr[t], v1 = xr[t + 256], v2 = xr[t + 512];
    float s  = v0 + v1 + v2;
    float ss = v0*v0 + v1*v1 + v2*v2;
    #pragma unroll
    for (int o = 16; o > 0; o >>= 1) {
        s  += __shfl_xor_sync(0xffffffffu, s,  o);
        ss += __shfl_xor_sync(0xffffffffu, ss, o);
    }
    __shared__ float rs[8], rss[8];
    if ((t & 31) == 0) { rs[t >> 5] = s; rss[t >> 5] = ss; }
    __syncthreads();
    float S1 = 0.f, S2 = 0.f;
    #pragma unroll
    for (int i = 0; i < 8; i++) { S1 += rs[i]; S2 += rss[i]; }
    float mean = S1 * (1.0f / DD);
    float var  = S2 * (1.0f / DD) - mean * mean;
    float rstd = rsqrtf(var + 1e-6f);
    __half* orow = out + (size_t)row * DD;
    orow[t      ] = __float2half_rn((v0 - mean) * rstd * g[t      ] + b[t      ]);
    orow[t + 256] = __float2half_rn((v1 - mean) * rstd * g[t + 256] + b[t + 256]);
    orow[t + 512] = __float2half_rn((v2 - mean) * rstd * g[t + 512] + b[t + 512]);
}

// ---------------- weight transpose W[K,N] -> Wt[N,K] fp16 -------------------
__global__ __launch_bounds__(256) void transpose_kernel(const float* __restrict__ in,
                                                        __half* __restrict__ out,
                                                        int K, int N) {
    __shared__ float tile[32][33];
    int x  = blockIdx.x * 32 + threadIdx.x;
    int y0 = blockIdx.y * 32;
    #pragma unroll
    for (int i = threadIdx.y; i < 32; i += 8) {
        int y = y0 + i;
        if (x < N && y < K) tile[i][threadIdx.x] = in[(size_t)y * N + x];
    }
    __syncthreads();
    int ox  = y0 + threadIdx.x;
    int oy0 = blockIdx.x * 32;
    #pragma unroll
    for (int i = threadIdx.y; i < 32; i += 8) {
        int oy = oy0 + i;
        if (ox < K && oy < N) out[(size_t)oy * K + ox] = __float2half_rn(tile[threadIdx.x][i]);
    }
}

// ---------------- fp16 mma GEMM ---------------------------------------------
// C[M,N] = A[M,K](fp16) @ Wt[N,K]^T(fp16) + bias; modes:
//   0: write fp16 Ch;  1: GELU, write fp16 Ch;  2: +res(fp32), write fp32 Cf
// CTA 128x128, K-chunk 64 halves, 2-stage cp.async, smem rows 128B, XOR swizzle.
__global__ __launch_bounds__(256, 2) void gemm_fp16(const __half* __restrict__ A,
                                                    const __half* __restrict__ Wt,
                                                    const float* __restrict__ bias,
                                                    const float* __restrict__ res,
                                                    float* __restrict__ Cf,
                                                    __half* __restrict__ Ch,
                                                    int M, int N, int K, int mode) {
    extern __shared__ char smem[];
    uint32_t sbase = smem_u32(smem);
    const int tid = threadIdx.x, lane = tid & 31, w = tid >> 5;
    const int m0 = blockIdx.y * 128, n0 = blockIdx.x * 128;

    // cp.async: row r (0..127), chunks cb..cb+3 of 8 (16B each)
    const int r = tid >> 1, cb = (tid & 1) * 4;
    const __half* aP = A  + (size_t)(m0 + r) * K + cb * 8;
    const __half* bP = Wt + (size_t)(n0 + r) * K + cb * 8;
    uint32_t soff[4];
    #pragma unroll
    for (int j = 0; j < 4; j++)
        soff[j] = (uint32_t)r * 128u + (uint32_t)(((cb + j) ^ (r & 7)) << 4);

    const int NC = K / 64;

    float acc[2][8][4];
    #pragma unroll
    for (int mt = 0; mt < 2; mt++)
        #pragma unroll
        for (int nt = 0; nt < 8; nt++)
            #pragma unroll
            for (int i = 0; i < 4; i++) acc[mt][nt][i] = 0.f;

    const int L = lane & 7, gb = (lane >> 3) & 1, gh = lane >> 4;
    const int wm = (w >> 1) * 32, wn = (w & 1) * 64;
    uint32_t aRow[2], bRow[4];
    #pragma unroll
    for (int mt = 0; mt < 2; mt++) aRow[mt] = (uint32_t)(wm + mt * 16 + gb * 8 + L) * 128u;
    #pragma unroll
    for (int p = 0; p < 4; p++)    bRow[p]  = (uint32_t)(wn + p * 16 + gh * 8 + L) * 128u;

    // prologue
    {
        uint32_t sa = sbase, sb = sbase + 16384;
        #pragma unroll
        for (int j = 0; j < 4; j++) {
            cp_async16(sa + soff[j], aP + j * 8);
            cp_async16(sb + soff[j], bP + j * 8);
        }
        cp_commit();
    }

    for (int ch = 0; ch < NC; ch++) {
        if (ch + 1 < NC) {
            uint32_t na = sbase + (uint32_t)((ch + 1) & 1) * 32768u;
            uint32_t nb = na + 16384;
            const __half* ap = aP + (size_t)(ch + 1) * 64;
            const __half* bp = bP + (size_t)(ch + 1) * 64;
            #pragma unroll
            for (int j = 0; j < 4; j++) {
                cp_async16(na + soff[j], ap + j * 8);
                cp_async16(nb + soff[j], bp + j * 8);
            }
            cp_commit();
            asm volatile("cp.async.wait_group 1;" ::: "memory");
        } else {
            asm volatile("cp.async.wait_group 0;" ::: "memory");
        }
        __syncthreads();

        uint32_t stA = sbase + (uint32_t)(ch & 1) * 32768u;
        uint32_t stB = stA + 16384;

        #pragma unroll
        for (int ks = 0; ks < 4; ks++) {
            uint32_t af[2][4];
            #pragma unroll
            for (int mt = 0; mt < 2; mt++)
                ldm_x4(af[mt], stA + aRow[mt] + ((uint32_t)((2 * ks + gh) ^ L) << 4));
            uint32_t bf[4][4];
            #pragma unroll
            for (int p = 0; p < 4; p++)
                ldm_x4(bf[p], stB + bRow[p] + ((uint32_t)((2 * ks + gb) ^ L) << 4));
            #pragma unroll
            for (int mt = 0; mt < 2; mt++)
                #pragma unroll
                for (int p = 0; p < 4; p++) {
                    mma16816(acc[mt][2 * p],     af[mt], bf[p]);
                    mma16816(acc[mt][2 * p + 1], af[mt], bf[p] + 2);
                }
        }
        __syncthreads();
    }

    // epilogue
    const int lane4 = lane >> 2, u = lane & 3;
    #pragma unroll
    for (int mt = 0; mt < 2; mt++) {
        #pragma unroll
        for (int hf = 0; hf < 2; hf++) {
            int m = m0 + wm + mt * 16 + lane4 + hf * 8;
            #pragma unroll
            for (int nt = 0; nt < 8; nt++) {
                int n = n0 + wn + nt * 8 + 2 * u;
                float c0 = acc[mt][nt][hf * 2    ] + bias[n];
                float c1 = acc[mt][nt][hf * 2 + 1] + bias[n + 1];
                if (mode == 2) {
                    const float* rrow = res + (size_t)m * N;
                    Cf[(size_t)m * N + n]     = c0 + rrow[n];
                    Cf[(size_t)m * N + n + 1] = c1 + rrow[n + 1];
                } else {
                    if (mode == 1) {
                        c0 = 0.5f * c0 * (1.0f + erff(c0 * 0.70710678118654752f));
                        c1 = 0.5f * c1 * (1.0f + erff(c1 * 0.70710678118654752f));
                    }
                    __half2 hv = __floats2half2_rn(c0, c1);
                    *(__half2*)(Ch + (size_t)m * N + n) = hv;
                }
            }
        }
    }
}

// ---------------- 3D RoPE in place on fp16 q,k; scale q -----------------------
__global__ __launch_bounds__(256) void rope_kernel(const float* __restrict__ coords) {
    int idx = blockIdx.x * blockDim.x + threadIdx.x;
    int j    = idx & 15;
    int axis = (idx >> 4) % 3;
    int hd   = (idx / 48) & 7;
    int s    = (idx / 384) % SS;
    int b    =  idx / (384 * SS);
    float inv_freq = powf(10000.0f, -(float)j * (1.0f / 16.0f));
    float ang = coords[((size_t)(b * SS + s)) * 3 + axis] * inv_freq;
    float sn, cs;
    sincosf(ang, &sn, &cs);
    size_t base = (size_t)(b * SS + s) * (3 * DD) + hd * DHH + axis * 32 + j;
    __half* P = g_qkv + base;
    float q1 = __half2float(P[0]), q2 = __half2float(P[16]);
    P[0]  = __float2half_rn(SCALE_ATTN * (q1 * cs - q2 * sn));
    P[16] = __float2half_rn(SCALE_ATTN * (q1 * sn + q2 * cs));
    __half* Pk = P + DD;
    float k1 = __half2float(Pk[0]), k2 = __half2float(Pk[16]);
    Pk[0]  = __float2half_rn(k1 * cs - k2 * sn);
    Pk[16] = __float2half_rn(k1 * sn + k2 * cs);
}

// ---------------- fp16 tensor-core causal flash attention -------------------
// 64 q-rows/block, 128 threads (4 warps x 16 rows), kv tiles of 64.
// smem: Kq tile [64 rows][256B] (12 of 16 chunks used) = 16KB;
//       Vt [96 d][128B] (64 kv halves, swizzled) = 12KB.
__global__ __launch_bounds__(128) void attn_fp16() {
    __shared__ char sm[16384 + 12288];
    const uint32_t KqB = smem_u32(sm);
    const uint32_t VtB = KqB + 16384;
    const int t = threadIdx.x, lane = t & 31, w = t >> 5;
    const int L = lane & 7, gb = (lane >> 3) & 1, gh = lane >> 4;
    const int lane4 = lane >> 2, u = lane & 3;
    const int qt = blockIdx.x, bh = blockIdx.y;
    const int b = bh >> 3, h = bh & 7;
    const __half* qkv = g_qkv + (size_t)b * SS * (3 * DD);

    // staging map: 64 rows x 12 chunks, 6 per thread
    uint32_t dst[6]; int rows[6], cks[6];
    #pragma unroll
    for (int it = 0; it < 6; it++) {
        int idx = t + 128 * it;
        int row = idx / 12, c = idx % 12;
        rows[it] = row; cks[it] = c;
        dst[it] = KqB + (uint32_t)row * 256u +
                  ((uint32_t)((c & 8) | ((c ^ row) & 7)) << 4);
    }

    // ---- stage Q, extract fragments
    #pragma unroll
    for (int it = 0; it < 6; it++)
        cp_async16(dst[it], qkv + (size_t)(qt * 64 + rows[it]) * (3 * DD) + h * DHH + cks[it] * 8);
    cp_commit();
    asm volatile("cp.async.wait_group 0;" ::: "memory");
    __syncthreads();

    uint32_t qa[6][4];
    const uint32_t qRow = (uint32_t)(w * 16 + gb * 8 + L) * 256u;
    #pragma unroll
    for (int ks = 0; ks < 6; ks++) {
        int c = 2 * ks + gh;
        ldm_x4(qa[ks], KqB + qRow + ((uint32_t)((c & 8) | ((c ^ L) & 7)) << 4));
    }
    __syncthreads();

    float oacc[12][4];
    #pragma unroll
    for (int nt = 0; nt < 12; nt++)
        #pragma unroll
        for (int i = 0; i < 4; i++) oacc[nt][i] = 0.f;
    float m0 = -INFINITY, m1 = -INFINITY, l0 = 0.f, l1 = 0.f;

    // V transpose mapping: kv pair per thread
    const int kvp = (t & 31) * 2, dh = t >> 5;   // dh 0..3, 24 d each

    uint32_t kRow[4], vRow[6];
    #pragma unroll
    for (int p = 0; p < 4; p++) kRow[p] = (uint32_t)(p * 16 + gh * 8 + L) * 256u;
    #pragma unroll
    for (int p = 0; p < 6; p++) vRow[p] = (uint32_t)(p * 16 + gh * 8 + L) * 128u;

    for (int kt = 0; kt <= qt; kt++) {
        // K tile
        #pragma unroll
        for (int it = 0; it < 6; it++)
            cp_async16(dst[it], qkv + (size_t)(kt * 64 + rows[it]) * (3 * DD) + DD + h * DHH + cks[it] * 8);
        cp_commit();
        // V transpose: Vt[d][kv] half2 pairs, conflict-free STS.32
        {
            const __half* v0 = qkv + (size_t)(kt * 64 + kvp) * (3 * DD) + 2 * DD + h * DHH;
            const __half* v1 = v0 + 3 * DD;
            #pragma unroll
            for (int i = 0; i < 3; i++) {
                int d0 = dh * 24 + i * 8;
                uint4 xa = *(const uint4*)(v0 + d0);
                uint4 xb = *(const uint4*)(v1 + d0);
                const __half* ha = (const __half*)&xa;
                const __half* hb = (const __half*)&xb;
                #pragma unroll
                for (int j = 0; j < 8; j++) {
                    int d = d0 + j;
                    __half2 hv = __halves2half2(ha[j], hb[j]);
                    *(uint32_t*)(sm + 16384 + d * 128 +
                                 (((kvp >> 3) ^ (d & 7)) << 4) + (kvp & 7) * 2)
                        = *(uint32_t*)&hv;
                }
            }
        }
        asm volatile("cp.async.wait_group 0;" ::: "memory");
        __syncthreads();

        // ---- S = Q K^T
        float sfr[8][4];
        #pragma unroll
        for (int nt = 0; nt < 8; nt++)
            #pragma unroll
            for (int i = 0; i < 4; i++) sfr[nt][i] = 0.f;
        #pragma unroll
        for (int ks = 0; ks < 6; ks++) {
            int c = 2 * ks + gb;
            uint32_t coff = (uint32_t)((c & 8) | ((c ^ L) & 7)) << 4;
            #pragma unroll
            for (int p = 0; p < 4; p++) {
                uint32_t bf[4];
                ldm_x4(bf, KqB + kRow[p] + coff);
                mma16816(sfr[2 * p],     qa[ks], bf);
                mma16816(sfr[2 * p + 1], qa[ks], bf + 2);
            }
        }
        // ---- causal mask on diagonal
        if (kt == qt) {
            int r0 = w * 16 + lane4, r1 = r0 + 8;
            #pragma unroll
            for (int nt = 0; nt < 8; nt++) {
                int ca = nt * 8 + 2 * u, cbn = ca + 1;
                if (ca  > r0) sfr[nt][0] = -1e30f;
                if (cbn > r0) sfr[nt][1] = -1e30f;
                if (ca  > r1) sfr[nt][2] = -1e30f;
                if (cbn > r1) sfr[nt][3] = -1e30f;
            }
        }
        // ---- online softmax
        float mx0 = -INFINITY, mx1 = -INFINITY;
        #pragma unroll
        for (int nt = 0; nt < 8; nt++) {
            mx0 = fmaxf(mx0, fmaxf(sfr[nt][0], sfr[nt][1]));
            mx1 = fmaxf(mx1, fmaxf(sfr[nt][2], sfr[nt][3]));
        }
        mx0 = fmaxf(mx0, __shfl_xor_sync(0xffffffffu, mx0, 1));
        mx0 = fmaxf(mx0, __shfl_xor_sync(0xffffffffu, mx0, 2));
        mx1 = fmaxf(mx1, __shfl_xor_sync(0xffffffffu, mx1, 1));
        mx1 = fmaxf(mx1, __shfl_xor_sync(0xffffffffu, mx1, 2));
        float mn0 = fmaxf(m0, mx0), mn1 = fmaxf(m1, mx1);
        float al0 = __expf(m0 - mn0), al1 = __expf(m1 - mn1);
        m0 = mn0; m1 = mn1;
        l0 *= al0; l1 *= al1;
        #pragma unroll
        for (int nt = 0; nt < 12; nt++) {
            oacc[nt][0] *= al0; oacc[nt][1] *= al0;
            oacc[nt][2] *= al1; oacc[nt][3] *= al1;
        }
        #pragma unroll
        for (int nt = 0; nt < 8; nt++) {
            float p0 = __expf(sfr[nt][0] - mn0), p1 = __expf(sfr[nt][1] - mn0);
            float p2 = __expf(sfr[nt][2] - mn1), p3 = __expf(sfr[nt][3] - mn1);
            l0 += p0 + p1; l1 += p2 + p3;
            sfr[nt][0] = p0; sfr[nt][1] = p1; sfr[nt][2] = p2; sfr[nt][3] = p3;
        }
        // ---- O += P V : a-frags are pure register packs (no shuffles)
        #pragma unroll
        for (int j = 0; j < 4; j++) {
            uint32_t a[4];
            __half2 h0 = __floats2half2_rn(sfr[2*j][0],     sfr[2*j][1]);
            __half2 h1 = __floats2half2_rn(sfr[2*j][2],     sfr[2*j][3]);
            __half2 h2 = __floats2half2_rn(sfr[2*j + 1][0], sfr[2*j + 1][1]);
            __half2 h3 = __floats2half2_rn(sfr[2*j + 1][2], sfr[2*j + 1][3]);
            a[0] = *(uint32_t*)&h0; a[1] = *(uint32_t*)&h1;
            a[2] = *(uint32_t*)&h2; a[3] = *(uint32_t*)&h3;
            int c = 2 * j + gb;
            uint32_t coff = (uint32_t)((c ^ L) & 7) << 4;
            #pragma unroll
            for (int p = 0; p < 6; p++) {
                uint32_t bf[4];
                ldm_x4(bf, VtB + vRow[p] + coff);
                mma16816(oacc[2 * p],     a, bf);
                mma16816(oacc[2 * p + 1], a, bf + 2);
            }
        }
        __syncthreads();
    }

    // ---- finalize
    l0 += __shfl_xor_sync(0xffffffffu, l0, 1);
    l0 += __shfl_xor_sync(0xffffffffu, l0, 2);
    l1 += __shfl_xor_sync(0xffffffffu, l1, 1);
    l1 += __shfl_xor_sync(0xffffffffu, l1, 2);
    float i0 = 1.0f / l0, i1 = 1.0f / l1;
    int gr0 = qt * 64 + w * 16 + lane4, gr1 = gr0 + 8;
    __half* o0 = g_attn + (size_t)(b * SS + gr0) * DD + h * DHH;
    __half* o1 = g_attn + (size_t)(b * SS + gr1) * DD + h * DHH;
    #pragma unroll
    for (int nt = 0; nt < 12; nt++) {
        int c = nt * 8 + 2 * u;
        __half2 a0 = __floats2half2_rn(oacc[nt][0] * i0, oacc[nt][1] * i0);
        __half2 a1 = __floats2half2_rn(oacc[nt][2] * i1, oacc[nt][3] * i1);
        *(__half2*)(o0 + c) = a0;
        *(__half2*)(o1 + c) = a1;
    }
}

// ---------------- launch ----------------------------------------------------
extern "C" void kernel_launch(void* const* d_in, const int* in_sizes, int n_in,
                              void* d_out, int out_size) {
    const float* src     = (const float*)d_in[0];
    const float* coords  = (const float*)d_in[1];
    const float* norm1_g = (const float*)d_in[3];
    const float* norm1_b = (const float*)d_in[4];
    const float* qkv_w   = (const float*)d_in[5];
    const float* qkv_b   = (const float*)d_in[6];
    const float* proj_w  = (const float*)d_in[7];
    const float* proj_b  = (const float*)d_in[8];
    const float* norm2_g = (const float*)d_in[9];
    const float* norm2_b = (const float*)d_in[10];
    const float* fc1_w   = (const float*)d_in[11];
    const float* fc1_b   = (const float*)d_in[12];
    const float* fc2_w   = (const float*)d_in[13];
    const float* fc2_b   = (const float*)d_in[14];
    float* out = (float*)d_out;

    __half *xn, *qkvp, *attnp, *yp, *hp;
    __half *qkvwt, *projwt, *fc1wt, *fc2wt;
    float *x1p;
    cudaGetSymbolAddress((void**)&xn,    g_xn);
    cudaGetSymbolAddress((void**)&qkvp,  g_qkv);
    cudaGetSymbolAddress((void**)&attnp, g_attn);
    cudaGetSymbolAddress((void**)&x1p,   g_x1);
    cudaGetSymbolAddress((void**)&yp,    g_y);
    cudaGetSymbolAddress((void**)&hp,    g_h);
    cudaGetSymbolAddress((void**)&qkvwt, g_qkvwt);
    cudaGetSymbolAddress((void**)&projwt,g_projwt);
    cudaGetSymbolAddress((void**)&fc1wt, g_fc1wt);
    cudaGetSymbolAddress((void**)&fc2wt, g_fc2wt);

    static bool attr_set = false;
    if (!attr_set) {
        cudaFuncSetAttribute(gemm_fp16, cudaFuncAttributeMaxDynamicSharedMemorySize, 65536);
        attr_set = true;
    }

    // 0. transpose weights -> Wt[N,K] fp16
    transpose_kernel<<<dim3((3*DD)/32, DD/32), dim3(32,8)>>>(qkv_w, qkvwt, DD, 3*DD);
    transpose_kernel<<<dim3(DD/32, DD/32),     dim3(32,8)>>>(proj_w, projwt, DD, DD);
    transpose_kernel<<<dim3(HID/32, DD/32),    dim3(32,8)>>>(fc1_w, fc1wt, DD, HID);
    transpose_kernel<<<dim3(DD/32, HID/32),    dim3(32,8)>>>(fc2_w, fc2wt, HID, DD);

    // 1. LN1 -> fp16
    ln_kernel<<<BS, 256>>>(src, norm1_g, norm1_b, xn);
    // 2. QKV
    gemm_fp16<<<dim3((3*DD)/128, BS/128), 256, 65536>>>(
        xn, qkvwt, qkv_b, nullptr, nullptr, qkvp, BS, 3*DD, DD, 0);
    // 3. RoPE (scale q)
    rope_kernel<<<(BB * SS * HH * 3 * 16) / 256, 256>>>(coords);
    // 4. Attention
    attn_fp16<<<dim3(SS / 64, BB * HH), 128>>>();
    // 5. proj + residual(src) -> x1 (fp32)
    gemm_fp16<<<dim3(DD/128, BS/128), 256, 65536>>>(
        attnp, projwt, proj_b, src, x1p, nullptr, BS, DD, DD, 2);
    // 6. LN2 -> fp16
    ln_kernel<<<BS, 256>>>(x1p, norm2_g, norm2_b, yp);
    // 7. fc1 + GELU -> fp16
    gemm_fp16<<<dim3(HID/128, BS/128), 256, 65536>>>(
        yp, fc1wt, fc1_b, nullptr, nullptr, hp, BS, HID, DD, 1);
    // 8. fc2 + residual(x1) -> out (fp32)
    gemm_fp16<<<dim3(DD/128, BS/128), 256, 65536>>>(
        hp, fc2wt, fc2_b, x1p, out, nullptr, BS, DD, HID, 2);
}

// round 6
// speedup vs baseline: 7.2676x; 1.1239x over previous
#include <cuda_runtime.h>
#include <cuda_fp16.h>
#include <math.h>
#include <stdint.h>

#define BB 4
#define SS 2048
#define DD 768
#define HH 8
#define DHH 96
#define HID 3072
#define BS (BB*SS)          // 8192
#define SCALE_ATTN 0.1020620726159658f  // 1/sqrt(96)

// ---------------- scratch (device globals; no allocation) ----------------
__device__ __half g_xn  [(size_t)BS * DD];        // LN1 out (fp16)
__device__ __half g_qkv [(size_t)BS * 3 * DD];    // qkv fp16 (rope in-place)
__device__ __half g_attn[(size_t)BS * DD];        // attention out fp16
__device__ float  g_x1  [(size_t)BS * DD];        // src + proj(attn), fp32 trunk
__device__ __half g_y   [(size_t)BS * DD];        // LN2 out fp16
__device__ __half g_h   [(size_t)BS * HID];       // fc1+gelu out fp16
// fp16 weights, SAME layout as fp32 originals: W[K, N]
__device__ __half g_qkvw16[(size_t)DD * (3*DD)];
__device__ __half g_projw16[(size_t)DD * DD];
__device__ __half g_fc1w16 [(size_t)DD * HID];
__device__ __half g_fc2w16 [(size_t)HID * DD];

// ---------------- helpers ---------------------------------------------------
__device__ __forceinline__ void cp_async16(uint32_t dst, const void* src) {
    asm volatile("cp.async.cg.shared.global [%0], [%1], 16;" :: "r"(dst), "l"(src));
}
__device__ __forceinline__ void cp_commit() { asm volatile("cp.async.commit_group;" ::: "memory"); }
__device__ __forceinline__ uint32_t smem_u32(const void* p) {
    uint32_t a;
    asm("{ .reg .u64 t; cvta.to.shared.u64 t, %1; cvt.u32.u64 %0, t; }" : "=r"(a) : "l"(p));
    return a;
}
__device__ __forceinline__ void ldm_x4(uint32_t* r, uint32_t addr) {
    asm volatile("ldmatrix.sync.aligned.m8n8.x4.shared.b16 {%0,%1,%2,%3}, [%4];"
        : "=r"(r[0]), "=r"(r[1]), "=r"(r[2]), "=r"(r[3]) : "r"(addr));
}
__device__ __forceinline__ void ldm_x4t(uint32_t* r, uint32_t addr) {
    asm volatile("ldmatrix.sync.aligned.m8n8.x4.trans.shared.b16 {%0,%1,%2,%3}, [%4];"
        : "=r"(r[0]), "=r"(r[1]), "=r"(r[2]), "=r"(r[3]) : "r"(addr));
}
__device__ __forceinline__ void mma16816(float* c, const uint32_t* a, const uint32_t* b) {
    asm volatile(
        "mma.sync.aligned.m16n8k16.row.col.f32.f16.f16.f32 "
        "{%0,%1,%2,%3}, {%4,%5,%6,%7}, {%8,%9}, {%0,%1,%2,%3};"
        : "+f"(c[0]), "+f"(c[1]), "+f"(c[2]), "+f"(c[3])
        : "r"(a[0]), "r"(a[1]), "r"(a[2]), "r"(a[3]), "r"(b[0]), "r"(b[1]));
}

// ---------------- fused weight convert fp32 -> fp16 (no transpose) ----------
#define NW1 (DD*(3*DD)/4)
#define NW2 (DD*DD/4)
#define NW3 (DD*HID/4)
#define NW4 (HID*DD/4)
__global__ __launch_bounds__(256) void convert_w(const float* __restrict__ w1,
                                                 const float* __restrict__ w2,
                                                 const float* __restrict__ w3,
                                                 const float* __restrict__ w4) {
    int i = blockIdx.x * blockDim.x + threadIdx.x;
    const float* src; __half* dst; int off;
    if (i < NW1)                        { src = w1; dst = g_qkvw16;  off = i; }
    else if (i < NW1 + NW2)             { src = w2; dst = g_projw16; off = i - NW1; }
    else if (i < NW1 + NW2 + NW3)       { src = w3; dst = g_fc1w16;  off = i - NW1 - NW2; }
    else                                { src = w4; dst = g_fc2w16;  off = i - NW1 - NW2 - NW3; }
    float4 v = ((const float4*)src)[off];
    __half2 h0 = __floats2half2_rn(v.x, v.y);
    __half2 h1 = __floats2half2_rn(v.z, v.w);
    ((__half2*)dst)[off * 2]     = h0;
    ((__half2*)dst)[off * 2 + 1] = h1;
}

// ---------------- LayerNorm: one block per row, out fp16 --------------------
__global__ __launch_bounds__(256) void ln_kernel(const float* __restrict__ x,
                                                 const float* __restrict__ g,
                                                 const float* __restrict__ b,
                                                 __half* __restrict__ out) {
    int row = blockIdx.x;
    int t = threadIdx.x;
    const float* xr = x + (size_t)row * DD;
    float v0 = xr[t], v1 = xr[t + 256], v2 = xr[t + 512];
    float s  = v0 + v1 + v2;
    float ss = v0*v0 + v1*v1 + v2*v2;
    #pragma unroll
    for (int o = 16; o > 0; o >>= 1) {
        s  += __shfl_xor_sync(0xffffffffu, s,  o);
        ss += __shfl_xor_sync(0xffffffffu, ss, o);
    }
    __shared__ float rs[8], rss[8];
    if ((t & 31) == 0) { rs[t >> 5] = s; rss[t >> 5] = ss; }
    __syncthreads();
    float S1 = 0.f, S2 = 0.f;
    #pragma unroll
    for (int i = 0; i < 8; i++) { S1 += rs[i]; S2 += rss[i]; }
    float mean = S1 * (1.0f / DD);
    float var  = S2 * (1.0f / DD) - mean * mean;
    float rstd = rsqrtf(var + 1e-6f);
    __half* orow = out + (size_t)row * DD;
    orow[t      ] = __float2half_rn((v0 - mean) * rstd * g[t      ] + b[t      ]);
    orow[t + 256] = __float2half_rn((v1 - mean) * rstd * g[t + 256] + b[t + 256]);
    orow[t + 512] = __float2half_rn((v2 - mean) * rstd * g[t + 512] + b[t + 512]);
}

// ---------------- fp16 mma GEMM, B row-major [K,N] via ldmatrix.trans -------
// C[M,N] = A[M,K](fp16) @ W[K,N](fp16) + bias; modes:
//   0: write fp16 Ch;  1: GELU, write fp16 Ch;  2: +res(fp32), write fp32 Cf
// CTA 128x128, K-chunk 64, 2-stage cp.async.
// A tile: 128 rows x 128B;  B tile: 64 K-rows x 256B.
__global__ __launch_bounds__(256, 2) void gemm_fp16(const __half* __restrict__ A,
                                                    const __half* __restrict__ W,
                                                    const float* __restrict__ bias,
                                                    const float* __restrict__ res,
                                                    float* __restrict__ Cf,
                                                    __half* __restrict__ Ch,
                                                    int M, int N, int K, int mode) {
    extern __shared__ char smem[];
    uint32_t sbase = smem_u32(smem);
    const int tid = threadIdx.x, lane = tid & 31, w = tid >> 5;
    const int m0 = blockIdx.y * 128, n0 = blockIdx.x * 128;

    // A staging: row ar (0..127), 4 of 8 16B-chunks
    const int ar = tid >> 1, ac = (tid & 1) * 4;
    const __half* aP = A + (size_t)(m0 + ar) * K + ac * 8;
    uint32_t aoff[4];
    #pragma unroll
    for (int j = 0; j < 4; j++)
        aoff[j] = (uint32_t)ar * 128u + (uint32_t)(((ac + j) ^ (ar & 7)) << 4);
    // B staging: K-row br (0..63), 4 of 16 16B-chunks
    const int br = tid >> 2, bc = (tid & 3) * 4;
    const __half* bP = W + (size_t)br * N + n0 + bc * 8;
    uint32_t boff[4];
    #pragma unroll
    for (int j = 0; j < 4; j++) {
        int c = bc + j;
        boff[j] = (uint32_t)br * 256u + (uint32_t)(((c & 8) | ((c ^ br) & 7)) << 4);
    }

    const int NC = K / 64;

    float acc[2][8][4];
    #pragma unroll
    for (int mt = 0; mt < 2; mt++)
        #pragma unroll
        for (int nt = 0; nt < 8; nt++)
            #pragma unroll
            for (int i = 0; i < 4; i++) acc[mt][nt][i] = 0.f;

    const int L = lane & 7, gb = (lane >> 3) & 1, gh = lane >> 4;
    const int wm = (w >> 1) * 32, wn = (w & 1) * 64;
    uint32_t aRow[2];
    #pragma unroll
    for (int mt = 0; mt < 2; mt++) aRow[mt] = (uint32_t)(wm + mt * 16 + gb * 8 + L) * 128u;

    // prologue
    {
        uint32_t sa = sbase, sb = sbase + 16384;
        #pragma unroll
        for (int j = 0; j < 4; j++) {
            cp_async16(sa + aoff[j], aP + j * 8);
            cp_async16(sb + boff[j], bP + j * 8);
        }
        cp_commit();
    }

    for (int ch = 0; ch < NC; ch++) {
        if (ch + 1 < NC) {
            uint32_t na = sbase + (uint32_t)((ch + 1) & 1) * 32768u;
            uint32_t nb = na + 16384;
            const __half* ap = aP + (size_t)(ch + 1) * 64;
            const __half* bp = bP + (size_t)(ch + 1) * 64 * N;
            #pragma unroll
            for (int j = 0; j < 4; j++) {
                cp_async16(na + aoff[j], ap + j * 8);
                cp_async16(nb + boff[j], bp + j * 8);
            }
            cp_commit();
            asm volatile("cp.async.wait_group 1;" ::: "memory");
        } else {
            asm volatile("cp.async.wait_group 0;" ::: "memory");
        }
        __syncthreads();

        uint32_t stA = sbase + (uint32_t)(ch & 1) * 32768u;
        uint32_t stB = stA + 16384;

        #pragma unroll
        for (int ks = 0; ks < 4; ks++) {
            uint32_t af[2][4];
            #pragma unroll
            for (int mt = 0; mt < 2; mt++)
                ldm_x4(af[mt], stA + aRow[mt] + ((uint32_t)((2 * ks + gh) ^ L) << 4));
            // B: trans-ldmatrix from [K,N] tile; row = k within tile
            int krow = ks * 16 + L + gb * 8;
            uint32_t rb = stB + (uint32_t)krow * 256u;
            uint32_t bf[4][4];
            #pragma unroll
            for (int p = 0; p < 4; p++) {
                int c = (wn >> 3) + 2 * p + gh;
                ldm_x4t(bf[p], rb + ((uint32_t)((c & 8) | ((c ^ L) & 7)) << 4));
            }
            #pragma unroll
            for (int mt = 0; mt < 2; mt++)
                #pragma unroll
                for (int p = 0; p < 4; p++) {
                    mma16816(acc[mt][2 * p],     af[mt], bf[p]);
                    mma16816(acc[mt][2 * p + 1], af[mt], bf[p] + 2);
                }
        }
        __syncthreads();
    }

    // epilogue
    const int lane4 = lane >> 2, u = lane & 3;
    #pragma unroll
    for (int mt = 0; mt < 2; mt++) {
        #pragma unroll
        for (int hf = 0; hf < 2; hf++) {
            int m = m0 + wm + mt * 16 + lane4 + hf * 8;
            #pragma unroll
            for (int nt = 0; nt < 8; nt++) {
                int n = n0 + wn + nt * 8 + 2 * u;
                float c0 = acc[mt][nt][hf * 2    ] + bias[n];
                float c1 = acc[mt][nt][hf * 2 + 1] + bias[n + 1];
                if (mode == 2) {
                    const float* rrow = res + (size_t)m * N;
                    Cf[(size_t)m * N + n]     = c0 + rrow[n];
                    Cf[(size_t)m * N + n + 1] = c1 + rrow[n + 1];
                } else {
                    if (mode == 1) {
                        c0 = 0.5f * c0 * (1.0f + erff(c0 * 0.70710678118654752f));
                        c1 = 0.5f * c1 * (1.0f + erff(c1 * 0.70710678118654752f));
                    }
                    __half2 hv = __floats2half2_rn(c0, c1);
                    *(__half2*)(Ch + (size_t)m * N + n) = hv;
                }
            }
        }
    }
}

// ---------------- 3D RoPE in place on fp16 q,k; scale q ---------------------
__global__ __launch_bounds__(256) void rope_kernel(const float* __restrict__ coords) {
    int idx = blockIdx.x * blockDim.x + threadIdx.x;
    int j    = idx & 15;
    int axis = (idx >> 4) % 3;
    int hd   = (idx / 48) & 7;
    int s    = (idx / 384) % SS;
    int b    =  idx / (384 * SS);
    float inv_freq = powf(10000.0f, -(float)j * (1.0f / 16.0f));
    float ang = coords[((size_t)(b * SS + s)) * 3 + axis] * inv_freq;
    float sn, cs;
    sincosf(ang, &sn, &cs);
    size_t base = (size_t)(b * SS + s) * (3 * DD) + hd * DHH + axis * 32 + j;
    __half* P = g_qkv + base;
    float q1 = __half2float(P[0]), q2 = __half2float(P[16]);
    P[0]  = __float2half_rn(SCALE_ATTN * (q1 * cs - q2 * sn));
    P[16] = __float2half_rn(SCALE_ATTN * (q1 * sn + q2 * cs));
    __half* Pk = P + DD;
    float k1 = __half2float(Pk[0]), k2 = __half2float(Pk[16]);
    Pk[0]  = __float2half_rn(k1 * cs - k2 * sn);
    Pk[16] = __float2half_rn(k1 * sn + k2 * cs);
}

// ---------------- fp16 tensor-core causal flash attention -------------------
// 64 q-rows/block, 128 threads (4 warps x 16 rows), kv tiles of 64.
// smem 64KB dynamic: K0 @0, K1 @16K, V0 @32K, V1 @48K (each 64 rows x 256B).
// K read via non-trans ldmatrix; V read via trans ldmatrix (no manual transpose).
// Both double-buffered with cp.async prefetch of tile i+1 during compute of i.
__global__ __launch_bounds__(128) void attn_fp16() {
    extern __shared__ char sm[];
    const uint32_t base = smem_u32(sm);
    const int t = threadIdx.x, lane = t & 31, w = t >> 5;
    const int L = lane & 7, gb = (lane >> 3) & 1, gh = lane >> 4;
    const int lane4 = lane >> 2, u = lane & 3;
    const int qt = blockIdx.x, bh = blockIdx.y;
    const int b = bh >> 3, h = bh & 7;
    const __half* qkv = g_qkv + (size_t)b * SS * (3 * DD);

    // staging map: 64 rows x 12 chunks, 6 per thread (buffer-relative)
    uint32_t soff[6]; int rows[6], cks[6];
    #pragma unroll
    for (int it = 0; it < 6; it++) {
        int idx = t + 128 * it;
        int row = idx / 12, c = idx % 12;
        rows[it] = row; cks[it] = c;
        soff[it] = (uint32_t)row * 256u + ((uint32_t)((c & 8) | ((c ^ row) & 7)) << 4);
    }

    // ---- stage Q into K0, extract fragments
    #pragma unroll
    for (int it = 0; it < 6; it++)
        cp_async16(base + soff[it], qkv + (size_t)(qt * 64 + rows[it]) * (3 * DD) + h * DHH + cks[it] * 8);
    cp_commit();
    asm volatile("cp.async.wait_group 0;" ::: "memory");
    __syncthreads();

    uint32_t qa[6][4];
    const uint32_t qRow = (uint32_t)(w * 16 + gb * 8 + L) * 256u;
    #pragma unroll
    for (int ks = 0; ks < 6; ks++) {
        int c = 2 * ks + gh;
        ldm_x4(qa[ks], base + qRow + ((uint32_t)((c & 8) | ((c ^ L) & 7)) << 4));
    }
    __syncthreads();   // K0 about to be overwritten

    float oacc[12][4];
    #pragma unroll
    for (int nt = 0; nt < 12; nt++)
        #pragma unroll
        for (int i = 0; i < 4; i++) oacc[nt][i] = 0.f;
    float m0 = -INFINITY, m1 = -INFINITY, l0 = 0.f, l1 = 0.f;

    uint32_t kRow[4];
    #pragma unroll
    for (int p = 0; p < 4; p++) kRow[p] = (uint32_t)(p * 16 + gh * 8 + L) * 256u;

    // prologue: stage tile 0 into buffers 0
    #pragma unroll
    for (int it = 0; it < 6; it++) {
        const __half* kp = qkv + (size_t)rows[it] * (3 * DD) + DD + h * DHH + cks[it] * 8;
        cp_async16(base + soff[it], kp);
        cp_async16(base + 32768u + soff[it], kp + DD);
    }
    cp_commit();

    for (int kt = 0; kt <= qt; kt++) {
        uint32_t buf = (uint32_t)(kt & 1) * 16384u;
        if (kt < qt) {
            uint32_t nbuf = (uint32_t)((kt + 1) & 1) * 16384u;
            #pragma unroll
            for (int it = 0; it < 6; it++) {
                const __half* kp = qkv + (size_t)((kt + 1) * 64 + rows[it]) * (3 * DD) + DD + h * DHH + cks[it] * 8;
                cp_async16(base + nbuf + soff[it], kp);
                cp_async16(base + 32768u + nbuf + soff[it], kp + DD);
            }
            cp_commit();
            asm volatile("cp.async.wait_group 1;" ::: "memory");
        } else {
            asm volatile("cp.async.wait_group 0;" ::: "memory");
        }
        __syncthreads();

        const uint32_t kb = base + buf;
        const uint32_t vb = base + 32768u + buf;

        // ---- S = Q K^T
        float sfr[8][4];
        #pragma unroll
        for (int nt = 0; nt < 8; nt++)
            #pragma unroll
            for (int i = 0; i < 4; i++) sfr[nt][i] = 0.f;
        #pragma unroll
        for (int ks = 0; ks < 6; ks++) {
            int c = 2 * ks + gb;
            uint32_t coff = (uint32_t)((c & 8) | ((c ^ L) & 7)) << 4;
            #pragma unroll
            for (int p = 0; p < 4; p++) {
                uint32_t bf[4];
                ldm_x4(bf, kb + kRow[p] + coff);
                mma16816(sfr[2 * p],     qa[ks], bf);
                mma16816(sfr[2 * p + 1], qa[ks], bf + 2);
            }
        }
        // ---- causal mask on diagonal
        if (kt == qt) {
            int r0 = w * 16 + lane4, r1 = r0 + 8;
            #pragma unroll
            for (int nt = 0; nt < 8; nt++) {
                int ca = nt * 8 + 2 * u, cbn = ca + 1;
                if (ca  > r0) sfr[nt][0] = -1e30f;
                if (cbn > r0) sfr[nt][1] = -1e30f;
                if (ca  > r1) sfr[nt][2] = -1e30f;
                if (cbn > r1) sfr[nt][3] = -1e30f;
            }
        }
        // ---- online softmax
        float mx0 = -INFINITY, mx1 = -INFINITY;
        #pragma unroll
        for (int nt = 0; nt < 8; nt++) {
            mx0 = fmaxf(mx0, fmaxf(sfr[nt][0], sfr[nt][1]));
            mx1 = fmaxf(mx1, fmaxf(sfr[nt][2], sfr[nt][3]));
        }
        mx0 = fmaxf(mx0, __shfl_xor_sync(0xffffffffu, mx0, 1));
        mx0 = fmaxf(mx0, __shfl_xor_sync(0xffffffffu, mx0, 2));
        mx1 = fmaxf(mx1, __shfl_xor_sync(0xffffffffu, mx1, 1));
        mx1 = fmaxf(mx1, __shfl_xor_sync(0xffffffffu, mx1, 2));
        float mn0 = fmaxf(m0, mx0), mn1 = fmaxf(m1, mx1);
        float al0 = __expf(m0 - mn0), al1 = __expf(m1 - mn1);
        m0 = mn0; m1 = mn1;
        l0 *= al0; l1 *= al1;
        #pragma unroll
        for (int nt = 0; nt < 12; nt++) {
            oacc[nt][0] *= al0; oacc[nt][1] *= al0;
            oacc[nt][2] *= al1; oacc[nt][3] *= al1;
        }
        #pragma unroll
        for (int nt = 0; nt < 8; nt++) {
            float p0 = __expf(sfr[nt][0] - mn0), p1 = __expf(sfr[nt][1] - mn0);
            float p2 = __expf(sfr[nt][2] - mn1), p3 = __expf(sfr[nt][3] - mn1);
            l0 += p0 + p1; l1 += p2 + p3;
            sfr[nt][0] = p0; sfr[nt][1] = p1; sfr[nt][2] = p2; sfr[nt][3] = p3;
        }
        // ---- O += P V : V read via trans-ldmatrix from [kv][dh] tile
        #pragma unroll
        for (int j = 0; j < 4; j++) {
            uint32_t a[4];
            __half2 h0 = __floats2half2_rn(sfr[2*j][0],     sfr[2*j][1]);
            __half2 h1 = __floats2half2_rn(sfr[2*j][2],     sfr[2*j][3]);
            __half2 h2 = __floats2half2_rn(sfr[2*j + 1][0], sfr[2*j + 1][1]);
            __half2 h3 = __floats2half2_rn(sfr[2*j + 1][2], sfr[2*j + 1][3]);
            a[0] = *(uint32_t*)&h0; a[1] = *(uint32_t*)&h1;
            a[2] = *(uint32_t*)&h2; a[3] = *(uint32_t*)&h3;
            uint32_t rv = vb + (uint32_t)(j * 16 + L + gb * 8) * 256u;
            #pragma unroll
            for (int p = 0; p < 6; p++) {
                int c = 2 * p + gh;
                uint32_t bf[4];
                ldm_x4t(bf, rv + ((uint32_t)((c & 8) | ((c ^ L) & 7)) << 4));
                mma16816(oacc[2 * p],     a, bf);
                mma16816(oacc[2 * p + 1], a, bf + 2);
            }
        }
        __syncthreads();
    }

    // ---- finalize
    l0 += __shfl_xor_sync(0xffffffffu, l0, 1);
    l0 += __shfl_xor_sync(0xffffffffu, l0, 2);
    l1 += __shfl_xor_sync(0xffffffffu, l1, 1);
    l1 += __shfl_xor_sync(0xffffffffu, l1, 2);
    float i0 = 1.0f / l0, i1 = 1.0f / l1;
    int gr0 = qt * 64 + w * 16 + lane4, gr1 = gr0 + 8;
    __half* o0 = g_attn + (size_t)(b * SS + gr0) * DD + h * DHH;
    __half* o1 = g_attn + (size_t)(b * SS + gr1) * DD + h * DHH;
    #pragma unroll
    for (int nt = 0; nt < 12; nt++) {
        int c = nt * 8 + 2 * u;
        __half2 a0 = __floats2half2_rn(oacc[nt][0] * i0, oacc[nt][1] * i0);
        __half2 a1 = __floats2half2_rn(oacc[nt][2] * i1, oacc[nt][3] * i1);
        *(__half2*)(o0 + c) = a0;
        *(__half2*)(o1 + c) = a1;
    }
}

// ---------------- launch ----------------------------------------------------
extern "C" void kernel_launch(void* const* d_in, const int* in_sizes, int n_in,
                              void* d_out, int out_size) {
    const float* src     = (const float*)d_in[0];
    const float* coords  = (const float*)d_in[1];
    const float* norm1_g = (const float*)d_in[3];
    const float* norm1_b = (const float*)d_in[4];
    const float* qkv_w   = (const float*)d_in[5];
    const float* qkv_b   = (const float*)d_in[6];
    const float* proj_w  = (const float*)d_in[7];
    const float* proj_b  = (const float*)d_in[8];
    const float* norm2_g = (const float*)d_in[9];
    const float* norm2_b = (const float*)d_in[10];
    const float* fc1_w   = (const float*)d_in[11];
    const float* fc1_b   = (const float*)d_in[12];
    const float* fc2_w   = (const float*)d_in[13];
    const float* fc2_b   = (const float*)d_in[14];
    float* out = (float*)d_out;

    __half *xn, *qkvp, *attnp, *yp, *hp;
    __half *qkvw, *projw, *fc1w, *fc2w;
    float *x1p;
    cudaGetSymbolAddress((void**)&xn,    g_xn);
    cudaGetSymbolAddress((void**)&qkvp,  g_qkv);
    cudaGetSymbolAddress((void**)&attnp, g_attn);
    cudaGetSymbolAddress((void**)&x1p,   g_x1);
    cudaGetSymbolAddress((void**)&yp,    g_y);
    cudaGetSymbolAddress((void**)&hp,    g_h);
    cudaGetSymbolAddress((void**)&qkvw,  g_qkvw16);
    cudaGetSymbolAddress((void**)&projw, g_projw16);
    cudaGetSymbolAddress((void**)&fc1w,  g_fc1w16);
    cudaGetSymbolAddress((void**)&fc2w,  g_fc2w16);

    static bool attr_set = false;
    if (!attr_set) {
        cudaFuncSetAttribute(gemm_fp16, cudaFuncAttributeMaxDynamicSharedMemorySize, 65536);
        cudaFuncSetAttribute(attn_fp16, cudaFuncAttributeMaxDynamicSharedMemorySize, 65536);
        attr_set = true;
    }

    // 0. fused weight convert (no transpose)
    convert_w<<<(NW1 + NW2 + NW3 + NW4) / 256, 256>>>(qkv_w, proj_w, fc1_w, fc2_w);
    // 1. LN1 -> fp16
    ln_kernel<<<BS, 256>>>(src, norm1_g, norm1_b, xn);
    // 2. QKV
    gemm_fp16<<<dim3((3*DD)/128, BS/128), 256, 65536>>>(
        xn, qkvw, qkv_b, nullptr, nullptr, qkvp, BS, 3*DD, DD, 0);
    // 3. RoPE (scale q)
    rope_kernel<<<(BB * SS * HH * 3 * 16) / 256, 256>>>(coords);
    // 4. Attention
    attn_fp16<<<dim3(SS / 64, BB * HH), 128, 65536>>>();
    // 5. proj + residual(src) -> x1 (fp32)
    gemm_fp16<<<dim3(DD/128, BS/128), 256, 65536>>>(
        attnp, projw, proj_b, src, x1p, nullptr, BS, DD, DD, 2);
    // 6. LN2 -> fp16
    ln_kernel<<<BS, 256>>>(x1p, norm2_g, norm2_b, yp);
    // 7. fc1 + GELU -> fp16
    gemm_fp16<<<dim3(HID/128, BS/128), 256, 65536>>>(
        yp, fc1w, fc1_b, nullptr, nullptr, hp, BS, HID, DD, 1);
    // 8. fc2 + residual(x1) -> out (fp32)
    gemm_fp16<<<dim3(DD/128, BS/128), 256, 65536>>>(
        hp, fc2w, fc2_b, x1p, out, nullptr, BS, DD, HID, 2);
}

// round 7
// speedup vs baseline: 7.4642x; 1.0271x over previous
#include <cuda_runtime.h>
#include <cuda_fp16.h>
#include <math.h>
#include <stdint.h>

#define BB 4
#define SS 2048
#define DD 768
#define HH 8
#define DHH 96
#define HID 3072
#define BS (BB*SS)          // 8192
#define SCALE_ATTN 0.1020620726159658f  // 1/sqrt(96)
#define NLOG_16 0.575646273248511f      // ln(10000)/16

// ---------------- scratch (device globals; no allocation) ----------------
__device__ __half g_xn  [(size_t)BS * DD];        // LN1 out (fp16)
__device__ __half g_qkv [(size_t)BS * 3 * DD];    // qkv fp16 (rope fused in GEMM)
__device__ __half g_attn[(size_t)BS * DD];        // attention out fp16
__device__ float  g_x1  [(size_t)BS * DD];        // src + proj(attn), fp32 trunk
__device__ __half g_y   [(size_t)BS * DD];        // LN2 out fp16
__device__ __half g_h   [(size_t)BS * HID];       // fc1+gelu out fp16
// fp16 weights, SAME layout as fp32 originals: W[K, N]
__device__ __half g_qkvw16[(size_t)DD * (3*DD)];
__device__ __half g_projw16[(size_t)DD * DD];
__device__ __half g_fc1w16 [(size_t)DD * HID];
__device__ __half g_fc2w16 [(size_t)HID * DD];

// ---------------- helpers ---------------------------------------------------
__device__ __forceinline__ void cp_async16(uint32_t dst, const void* src) {
    asm volatile("cp.async.cg.shared.global [%0], [%1], 16;" :: "r"(dst), "l"(src));
}
__device__ __forceinline__ void cp_commit() { asm volatile("cp.async.commit_group;" ::: "memory"); }
__device__ __forceinline__ uint32_t smem_u32(const void* p) {
    uint32_t a;
    asm("{ .reg .u64 t; cvta.to.shared.u64 t, %1; cvt.u32.u64 %0, t; }" : "=r"(a) : "l"(p));
    return a;
}
__device__ __forceinline__ void ldm_x4(uint32_t* r, uint32_t addr) {
    asm volatile("ldmatrix.sync.aligned.m8n8.x4.shared.b16 {%0,%1,%2,%3}, [%4];"
        : "=r"(r[0]), "=r"(r[1]), "=r"(r[2]), "=r"(r[3]) : "r"(addr));
}
__device__ __forceinline__ void ldm_x4t(uint32_t* r, uint32_t addr) {
    asm volatile("ldmatrix.sync.aligned.m8n8.x4.trans.shared.b16 {%0,%1,%2,%3}, [%4];"
        : "=r"(r[0]), "=r"(r[1]), "=r"(r[2]), "=r"(r[3]) : "r"(addr));
}
__device__ __forceinline__ void mma16816(float* c, const uint32_t* a, const uint32_t* b) {
    asm volatile(
        "mma.sync.aligned.m16n8k16.row.col.f32.f16.f16.f32 "
        "{%0,%1,%2,%3}, {%4,%5,%6,%7}, {%8,%9}, {%0,%1,%2,%3};"
        : "+f"(c[0]), "+f"(c[1]), "+f"(c[2]), "+f"(c[3])
        : "r"(a[0]), "r"(a[1]), "r"(a[2]), "r"(a[3]), "r"(b[0]), "r"(b[1]));
}

// ---------------- fused weight convert fp32 -> fp16 (no transpose) ----------
#define NW1 (DD*(3*DD)/4)
#define NW2 (DD*DD/4)
#define NW3 (DD*HID/4)
#define NW4 (HID*DD/4)
__global__ __launch_bounds__(256) void convert_w(const float* __restrict__ w1,
                                                 const float* __restrict__ w2,
                                                 const float* __restrict__ w3,
                                                 const float* __restrict__ w4) {
    int i = blockIdx.x * blockDim.x + threadIdx.x;
    const float* src; __half* dst; int off;
    if (i < NW1)                        { src = w1; dst = g_qkvw16;  off = i; }
    else if (i < NW1 + NW2)             { src = w2; dst = g_projw16; off = i - NW1; }
    else if (i < NW1 + NW2 + NW3)       { src = w3; dst = g_fc1w16;  off = i - NW1 - NW2; }
    else                                { src = w4; dst = g_fc2w16;  off = i - NW1 - NW2 - NW3; }
    float4 v = ((const float4*)src)[off];
    __half2 h0 = __floats2half2_rn(v.x, v.y);
    __half2 h1 = __floats2half2_rn(v.z, v.w);
    ((__half2*)dst)[off * 2]     = h0;
    ((__half2*)dst)[off * 2 + 1] = h1;
}

// ---------------- LayerNorm: one block per row, out fp16 --------------------
__global__ __launch_bounds__(256) void ln_kernel(const float* __restrict__ x,
                                                 const float* __restrict__ g,
                                                 const float* __restrict__ b,
                                                 __half* __restrict__ out) {
    int row = blockIdx.x;
    int t = threadIdx.x;
    const float* xr = x + (size_t)row * DD;
    float v0 = xr[t], v1 = xr[t + 256], v2 = xr[t + 512];
    float s  = v0 + v1 + v2;
    float ss = v0*v0 + v1*v1 + v2*v2;
    #pragma unroll
    for (int o = 16; o > 0; o >>= 1) {
        s  += __shfl_xor_sync(0xffffffffu, s,  o);
        ss += __shfl_xor_sync(0xffffffffu, ss, o);
    }
    __shared__ float rs[8], rss[8];
    if ((t & 31) == 0) { rs[t >> 5] = s; rss[t >> 5] = ss; }
    __syncthreads();
    float S1 = 0.f, S2 = 0.f;
    #pragma unroll
    for (int i = 0; i < 8; i++) { S1 += rs[i]; S2 += rss[i]; }
    float mean = S1 * (1.0f / DD);
    float var  = S2 * (1.0f / DD) - mean * mean;
    float rstd = rsqrtf(var + 1e-6f);
    __half* orow = out + (size_t)row * DD;
    orow[t      ] = __float2half_rn((v0 - mean) * rstd * g[t      ] + b[t      ]);
    orow[t + 256] = __float2half_rn((v1 - mean) * rstd * g[t + 256] + b[t + 256]);
    orow[t + 512] = __float2half_rn((v2 - mean) * rstd * g[t + 512] + b[t + 512]);
}

// ---------------- fp16 mma GEMM, B row-major [K,N] via ldmatrix.trans -------
// C[M,N] = A[M,K](fp16) @ W[K,N](fp16) + bias; modes:
//   0: write fp16 Ch;  1: GELU, fp16 Ch;  2: +res(fp32), fp32 Cf;
//   3: fused 3D-RoPE epilogue (QKV): rotate q,k pairs, scale q, fp16 Ch
// CTA 128x128, K-chunk 64, 3-stage cp.async, 1 barrier per chunk.
__global__ __launch_bounds__(256, 2) void gemm_fp16(const __half* __restrict__ A,
                                                    const __half* __restrict__ W,
                                                    const float* __restrict__ bias,
                                                    const float* __restrict__ res,
                                                    float* __restrict__ Cf,
                                                    __half* __restrict__ Ch,
                                                    const float* __restrict__ coords,
                                                    int M, int N, int K, int mode) {
    extern __shared__ char smem[];
    uint32_t sbase = smem_u32(smem);
    const int tid = threadIdx.x, lane = tid & 31, w = tid >> 5;
    const int m0 = blockIdx.y * 128, n0 = blockIdx.x * 128;

    // A staging: row ar (0..127), 4 of 8 16B-chunks
    const int ar = tid >> 1, ac = (tid & 1) * 4;
    const __half* aP = A + (size_t)(m0 + ar) * K + ac * 8;
    uint32_t aoff[4];
    #pragma unroll
    for (int j = 0; j < 4; j++)
        aoff[j] = (uint32_t)ar * 128u + (uint32_t)(((ac + j) ^ (ar & 7)) << 4);
    // B staging: K-row br (0..63), 4 of 16 16B-chunks
    const int br = tid >> 2, bc = (tid & 3) * 4;
    const __half* bP = W + (size_t)br * N + n0 + bc * 8;
    uint32_t boff[4];
    #pragma unroll
    for (int j = 0; j < 4; j++) {
        int c = bc + j;
        boff[j] = (uint32_t)br * 256u + (uint32_t)(((c & 8) | ((c ^ br) & 7)) << 4);
    }

    const int NC = K / 64;

    float acc[2][8][4];
    #pragma unroll
    for (int mt = 0; mt < 2; mt++)
        #pragma unroll
        for (int nt = 0; nt < 8; nt++)
            #pragma unroll
            for (int i = 0; i < 4; i++) acc[mt][nt][i] = 0.f;

    const int L = lane & 7, gb = (lane >> 3) & 1, gh = lane >> 4;
    const int wm = (w >> 1) * 32, wn = (w & 1) * 64;
    uint32_t aRow[2];
    #pragma unroll
    for (int mt = 0; mt < 2; mt++) aRow[mt] = (uint32_t)(wm + mt * 16 + gb * 8 + L) * 128u;

    // prologue: stage chunks 0 and 1
    #pragma unroll
    for (int pre = 0; pre < 2; pre++) {
        if (pre < NC) {
            uint32_t sa = sbase + (uint32_t)pre * 32768u;
            uint32_t sb = sa + 16384;
            const __half* ap = aP + (size_t)pre * 64;
            const __half* bp = bP + (size_t)pre * 64 * N;
            #pragma unroll
            for (int j = 0; j < 4; j++) {
                cp_async16(sa + aoff[j], ap + j * 8);
                cp_async16(sb + boff[j], bp + j * 8);
            }
            cp_commit();
        }
    }

    for (int ch = 0; ch < NC; ch++) {
        if (ch < NC - 1) { asm volatile("cp.async.wait_group 1;" ::: "memory"); }
        else             { asm volatile("cp.async.wait_group 0;" ::: "memory"); }
        __syncthreads();   // chunk ch landed; all warps done reading buffer (ch-1)%3

        if (ch + 2 < NC) {
            uint32_t na = sbase + (uint32_t)((ch + 2) % 3) * 32768u;
            uint32_t nb = na + 16384;
            const __half* ap = aP + (size_t)(ch + 2) * 64;
            const __half* bp = bP + (size_t)(ch + 2) * 64 * N;
            #pragma unroll
            for (int j = 0; j < 4; j++) {
                cp_async16(na + aoff[j], ap + j * 8);
                cp_async16(nb + boff[j], bp + j * 8);
            }
            cp_commit();
        }

        uint32_t stA = sbase + (uint32_t)(ch % 3) * 32768u;
        uint32_t stB = stA + 16384;

        #pragma unroll
        for (int ks = 0; ks < 4; ks++) {
            uint32_t af[2][4];
            #pragma unroll
            for (int mt = 0; mt < 2; mt++)
                ldm_x4(af[mt], stA + aRow[mt] + ((uint32_t)((2 * ks + gh) ^ L) << 4));
            int krow = ks * 16 + L + gb * 8;
            uint32_t rb = stB + (uint32_t)krow * 256u;
            uint32_t bf[4][4];
            #pragma unroll
            for (int p = 0; p < 4; p++) {
                int c = (wn >> 3) + 2 * p + gh;
                ldm_x4t(bf[p], rb + ((uint32_t)((c & 8) | ((c ^ L) & 7)) << 4));
            }
            #pragma unroll
            for (int mt = 0; mt < 2; mt++)
                #pragma unroll
                for (int p = 0; p < 4; p++) {
                    mma16816(acc[mt][2 * p],     af[mt], bf[p]);
                    mma16816(acc[mt][2 * p + 1], af[mt], bf[p] + 2);
                }
        }
    }

    // ---------------- epilogue ----------------
    const int lane4 = lane >> 2, u = lane & 3;
    if (mode == 3) {
        // fused 3D RoPE on q,k columns (+ 1/sqrt(dh) scale on q); v plain.
        #pragma unroll
        for (int mt = 0; mt < 2; mt++) {
            #pragma unroll
            for (int hf = 0; hf < 2; hf++) {
                int m = m0 + wm + mt * 16 + lane4 + hf * 8;
                const float* cr = coords + (size_t)m * 3;
                __half* crow = Ch + (size_t)m * N;
                #pragma unroll
                for (int bi = 0; bi < 2; bi++) {
                    int colblk = n0 + wn + bi * 32;
                    int part = colblk / DD;          // 0=q,1=k,2=v
                    if (part == 2) {
                        #pragma unroll
                        for (int pp = 0; pp < 4; pp++) {
                            int nt = bi * 4 + pp;
                            int n = n0 + wn + nt * 8 + 2 * u;
                            float c0 = acc[mt][nt][hf * 2    ] + bias[n];
                            float c1 = acc[mt][nt][hf * 2 + 1] + bias[n + 1];
                            *(__half2*)(crow + n) = __floats2half2_rn(c0, c1);
                        }
                    } else {
                        int axis = (colblk % DHH) >> 5;
                        float coord = cr[axis];
                        float sc = (part == 0) ? SCALE_ATTN : 1.0f;
                        #pragma unroll
                        for (int pp = 0; pp < 2; pp++) {
                            int nt1 = bi * 4 + pp, nt2 = nt1 + 2;
                            int n1 = n0 + wn + nt1 * 8 + 2 * u;
                            int n2 = n1 + 16;
                            int j0 = pp * 8 + 2 * u;
                            float ang0 = coord * __expf((float)j0       * -NLOG_16);
                            float ang1 = coord * __expf((float)(j0 + 1) * -NLOG_16);
                            float sn0, cs0, sn1, cs1;
                            __sincosf(ang0, &sn0, &cs0);
                            __sincosf(ang1, &sn1, &cs1);
                            float x10 = acc[mt][nt1][hf * 2    ] + bias[n1];
                            float x11 = acc[mt][nt1][hf * 2 + 1] + bias[n1 + 1];
                            float x20 = acc[mt][nt2][hf * 2    ] + bias[n2];
                            float x21 = acc[mt][nt2][hf * 2 + 1] + bias[n2 + 1];
                            *(__half2*)(crow + n1) = __floats2half2_rn(
                                sc * (x10 * cs0 - x20 * sn0), sc * (x11 * cs1 - x21 * sn1));
                            *(__half2*)(crow + n2) = __floats2half2_rn(
                                sc * (x10 * sn0 + x20 * cs0), sc * (x11 * sn1 + x21 * cs1));
                        }
                    }
                }
            }
        }
    } else {
        #pragma unroll
        for (int mt = 0; mt < 2; mt++) {
            #pragma unroll
            for (int hf = 0; hf < 2; hf++) {
                int m = m0 + wm + mt * 16 + lane4 + hf * 8;
                #pragma unroll
                for (int nt = 0; nt < 8; nt++) {
                    int n = n0 + wn + nt * 8 + 2 * u;
                    float c0 = acc[mt][nt][hf * 2    ] + bias[n];
                    float c1 = acc[mt][nt][hf * 2 + 1] + bias[n + 1];
                    if (mode == 2) {
                        const float* rrow = res + (size_t)m * N;
                        Cf[(size_t)m * N + n]     = c0 + rrow[n];
                        Cf[(size_t)m * N + n + 1] = c1 + rrow[n + 1];
                    } else {
                        if (mode == 1) {
                            c0 = 0.5f * c0 * (1.0f + erff(c0 * 0.70710678118654752f));
                            c1 = 0.5f * c1 * (1.0f + erff(c1 * 0.70710678118654752f));
                        }
                        *(__half2*)(Ch + (size_t)m * N + n) = __floats2half2_rn(c0, c1);
                    }
                }
            }
        }
    }
}

// ---------------- fp16 tensor-core causal flash attention -------------------
// 64 q-rows/block, 128 threads (4 warps x 16 rows), kv tiles of 64.
// smem 64KB: K0 @0, K1 @16K, V0 @32K, V1 @48K (each 64 rows x 256B).
__global__ __launch_bounds__(128) void attn_fp16() {
    extern __shared__ char sm[];
    const uint32_t base = smem_u32(sm);
    const int t = threadIdx.x, lane = t & 31, w = t >> 5;
    const int L = lane & 7, gb = (lane >> 3) & 1, gh = lane >> 4;
    const int lane4 = lane >> 2, u = lane & 3;
    const int qt = blockIdx.x, bh = blockIdx.y;
    const int b = bh >> 3, h = bh & 7;
    const __half* qkv = g_qkv + (size_t)b * SS * (3 * DD);

    uint32_t soff[6]; int rows[6], cks[6];
    #pragma unroll
    for (int it = 0; it < 6; it++) {
        int idx = t + 128 * it;
        int row = idx / 12, c = idx % 12;
        rows[it] = row; cks[it] = c;
        soff[it] = (uint32_t)row * 256u + ((uint32_t)((c & 8) | ((c ^ row) & 7)) << 4);
    }

    // ---- stage Q into K0, extract fragments
    #pragma unroll
    for (int it = 0; it < 6; it++)
        cp_async16(base + soff[it], qkv + (size_t)(qt * 64 + rows[it]) * (3 * DD) + h * DHH + cks[it] * 8);
    cp_commit();
    asm volatile("cp.async.wait_group 0;" ::: "memory");
    __syncthreads();

    uint32_t qa[6][4];
    const uint32_t qRow = (uint32_t)(w * 16 + gb * 8 + L) * 256u;
    #pragma unroll
    for (int ks = 0; ks < 6; ks++) {
        int c = 2 * ks + gh;
        ldm_x4(qa[ks], base + qRow + ((uint32_t)((c & 8) | ((c ^ L) & 7)) << 4));
    }
    __syncthreads();

    float oacc[12][4];
    #pragma unroll
    for (int nt = 0; nt < 12; nt++)
        #pragma unroll
        for (int i = 0; i < 4; i++) oacc[nt][i] = 0.f;
    float m0 = -INFINITY, m1 = -INFINITY, l0 = 0.f, l1 = 0.f;

    uint32_t kRow[4];
    #pragma unroll
    for (int p = 0; p < 4; p++) kRow[p] = (uint32_t)(p * 16 + gh * 8 + L) * 256u;

    // prologue: stage tile 0
    #pragma unroll
    for (int it = 0; it < 6; it++) {
        const __half* kp = qkv + (size_t)rows[it] * (3 * DD) + DD + h * DHH + cks[it] * 8;
        cp_async16(base + soff[it], kp);
        cp_async16(base + 32768u + soff[it], kp + DD);
    }
    cp_commit();

    for (int kt = 0; kt <= qt; kt++) {
        uint32_t buf = (uint32_t)(kt & 1) * 16384u;
        if (kt < qt) {
            uint32_t nbuf = (uint32_t)((kt + 1) & 1) * 16384u;
            #pragma unroll
            for (int it = 0; it < 6; it++) {
                const __half* kp = qkv + (size_t)((kt + 1) * 64 + rows[it]) * (3 * DD) + DD + h * DHH + cks[it] * 8;
                cp_async16(base + nbuf + soff[it], kp);
                cp_async16(base + 32768u + nbuf + soff[it], kp + DD);
            }
            cp_commit();
            asm volatile("cp.async.wait_group 1;" ::: "memory");
        } else {
            asm volatile("cp.async.wait_group 0;" ::: "memory");
        }
        __syncthreads();

        const uint32_t kb = base + buf;
        const uint32_t vb = base + 32768u + buf;

        // ---- S = Q K^T
        float sfr[8][4];
        #pragma unroll
        for (int nt = 0; nt < 8; nt++)
            #pragma unroll
            for (int i = 0; i < 4; i++) sfr[nt][i] = 0.f;
        #pragma unroll
        for (int ks = 0; ks < 6; ks++) {
            int c = 2 * ks + gb;
            uint32_t coff = (uint32_t)((c & 8) | ((c ^ L) & 7)) << 4;
            #pragma unroll
            for (int p = 0; p < 4; p++) {
                uint32_t bf[4];
                ldm_x4(bf, kb + kRow[p] + coff);
                mma16816(sfr[2 * p],     qa[ks], bf);
                mma16816(sfr[2 * p + 1], qa[ks], bf + 2);
            }
        }
        // ---- causal mask on diagonal
        if (kt == qt) {
            int r0 = w * 16 + lane4, r1 = r0 + 8;
            #pragma unroll
            for (int nt = 0; nt < 8; nt++) {
                int ca = nt * 8 + 2 * u, cbn = ca + 1;
                if (ca  > r0) sfr[nt][0] = -1e30f;
                if (cbn > r0) sfr[nt][1] = -1e30f;
                if (ca  > r1) sfr[nt][2] = -1e30f;
                if (cbn > r1) sfr[nt][3] = -1e30f;
            }
        }
        // ---- online softmax
        float mx0 = -INFINITY, mx1 = -INFINITY;
        #pragma unroll
        for (int nt = 0; nt < 8; nt++) {
            mx0 = fmaxf(mx0, fmaxf(sfr[nt][0], sfr[nt][1]));
            mx1 = fmaxf(mx1, fmaxf(sfr[nt][2], sfr[nt][3]));
        }
        mx0 = fmaxf(mx0, __shfl_xor_sync(0xffffffffu, mx0, 1));
        mx0 = fmaxf(mx0, __shfl_xor_sync(0xffffffffu, mx0, 2));
        mx1 = fmaxf(mx1, __shfl_xor_sync(0xffffffffu, mx1, 1));
        mx1 = fmaxf(mx1, __shfl_xor_sync(0xffffffffu, mx1, 2));
        float mn0 = fmaxf(m0, mx0), mn1 = fmaxf(m1, mx1);
        float al0 = __expf(m0 - mn0), al1 = __expf(m1 - mn1);
        m0 = mn0; m1 = mn1;
        l0 *= al0; l1 *= al1;
        #pragma unroll
        for (int nt = 0; nt < 12; nt++) {
            oacc[nt][0] *= al0; oacc[nt][1] *= al0;
            oacc[nt][2] *= al1; oacc[nt][3] *= al1;
        }
        #pragma unroll
        for (int nt = 0; nt < 8; nt++) {
            float p0 = __expf(sfr[nt][0] - mn0), p1 = __expf(sfr[nt][1] - mn0);
            float p2 = __expf(sfr[nt][2] - mn1), p3 = __expf(sfr[nt][3] - mn1);
            l0 += p0 + p1; l1 += p2 + p3;
            sfr[nt][0] = p0; sfr[nt][1] = p1; sfr[nt][2] = p2; sfr[nt][3] = p3;
        }
        // ---- O += P V : V via trans-ldmatrix
        #pragma unroll
        for (int j = 0; j < 4; j++) {
            uint32_t a[4];
            __half2 h0 = __floats2half2_rn(sfr[2*j][0],     sfr[2*j][1]);
            __half2 h1 = __floats2half2_rn(sfr[2*j][2],     sfr[2*j][3]);
            __half2 h2 = __floats2half2_rn(sfr[2*j + 1][0], sfr[2*j + 1][1]);
            __half2 h3 = __floats2half2_rn(sfr[2*j + 1][2], sfr[2*j + 1][3]);
            a[0] = *(uint32_t*)&h0; a[1] = *(uint32_t*)&h1;
            a[2] = *(uint32_t*)&h2; a[3] = *(uint32_t*)&h3;
            uint32_t rv = vb + (uint32_t)(j * 16 + L + gb * 8) * 256u;
            #pragma unroll
            for (int p = 0; p < 6; p++) {
                int c = 2 * p + gh;
                uint32_t bf[4];
                ldm_x4t(bf, rv + ((uint32_t)((c & 8) | ((c ^ L) & 7)) << 4));
                mma16816(oacc[2 * p],     a, bf);
                mma16816(oacc[2 * p + 1], a, bf + 2);
            }
        }
        __syncthreads();
    }

    // ---- finalize
    l0 += __shfl_xor_sync(0xffffffffu, l0, 1);
    l0 += __shfl_xor_sync(0xffffffffu, l0, 2);
    l1 += __shfl_xor_sync(0xffffffffu, l1, 1);
    l1 += __shfl_xor_sync(0xffffffffu, l1, 2);
    float i0 = 1.0f / l0, i1 = 1.0f / l1;
    int gr0 = qt * 64 + w * 16 + lane4, gr1 = gr0 + 8;
    __half* o0 = g_attn + (size_t)(b * SS + gr0) * DD + h * DHH;
    __half* o1 = g_attn + (size_t)(b * SS + gr1) * DD + h * DHH;
    #pragma unroll
    for (int nt = 0; nt < 12; nt++) {
        int c = nt * 8 + 2 * u;
        __half2 a0 = __floats2half2_rn(oacc[nt][0] * i0, oacc[nt][1] * i0);
        __half2 a1 = __floats2half2_rn(oacc[nt][2] * i1, oacc[nt][3] * i1);
        *(__half2*)(o0 + c) = a0;
        *(__half2*)(o1 + c) = a1;
    }
}

// ---------------- launch ----------------------------------------------------
extern "C" void kernel_launch(void* const* d_in, const int* in_sizes, int n_in,
                              void* d_out, int out_size) {
    const float* src     = (const float*)d_in[0];
    const float* coords  = (const float*)d_in[1];
    const float* norm1_g = (const float*)d_in[3];
    const float* norm1_b = (const float*)d_in[4];
    const float* qkv_w   = (const float*)d_in[5];
    const float* qkv_b   = (const float*)d_in[6];
    const float* proj_w  = (const float*)d_in[7];
    const float* proj_b  = (const float*)d_in[8];
    const float* norm2_g = (const float*)d_in[9];
    const float* norm2_b = (const float*)d_in[10];
    const float* fc1_w   = (const float*)d_in[11];
    const float* fc1_b   = (const float*)d_in[12];
    const float* fc2_w   = (const float*)d_in[13];
    const float* fc2_b   = (const float*)d_in[14];
    float* out = (float*)d_out;

    __half *xn, *qkvp, *attnp, *yp, *hp;
    __half *qkvw, *projw, *fc1w, *fc2w;
    float *x1p;
    cudaGetSymbolAddress((void**)&xn,    g_xn);
    cudaGetSymbolAddress((void**)&qkvp,  g_qkv);
    cudaGetSymbolAddress((void**)&attnp, g_attn);
    cudaGetSymbolAddress((void**)&x1p,   g_x1);
    cudaGetSymbolAddress((void**)&yp,    g_y);
    cudaGetSymbolAddress((void**)&hp,    g_h);
    cudaGetSymbolAddress((void**)&qkvw,  g_qkvw16);
    cudaGetSymbolAddress((void**)&projw, g_projw16);
    cudaGetSymbolAddress((void**)&fc1w,  g_fc1w16);
    cudaGetSymbolAddress((void**)&fc2w,  g_fc2w16);

    static bool attr_set = false;
    if (!attr_set) {
        cudaFuncSetAttribute(gemm_fp16, cudaFuncAttributeMaxDynamicSharedMemorySize, 98304);
        cudaFuncSetAttribute(attn_fp16, cudaFuncAttributeMaxDynamicSharedMemorySize, 65536);
        attr_set = true;
    }

    // 0. fused weight convert
    convert_w<<<(NW1 + NW2 + NW3 + NW4) / 256, 256>>>(qkv_w, proj_w, fc1_w, fc2_w);
    // 1. LN1 -> fp16
    ln_kernel<<<BS, 256>>>(src, norm1_g, norm1_b, xn);
    // 2. QKV + fused RoPE (+q scale)
    gemm_fp16<<<dim3((3*DD)/128, BS/128), 256, 98304>>>(
        xn, qkvw, qkv_b, nullptr, nullptr, qkvp, coords, BS, 3*DD, DD, 3);
    // 3. Attention
    attn_fp16<<<dim3(SS / 64, BB * HH), 128, 65536>>>();
    // 4. proj + residual(src) -> x1 (fp32)
    gemm_fp16<<<dim3(DD/128, BS/128), 256, 98304>>>(
        attnp, projw, proj_b, src, x1p, nullptr, nullptr, BS, DD, DD, 2);
    // 5. LN2 -> fp16
    ln_kernel<<<BS, 256>>>(x1p, norm2_g, norm2_b, yp);
    // 6. fc1 + GELU -> fp16
    gemm_fp16<<<dim3(HID/128, BS/128), 256, 98304>>>(
        yp, fc1w, fc1_b, nullptr, nullptr, hp, nullptr, BS, HID, DD, 1);
    // 7. fc2 + residual(x1) -> out (fp32)
    gemm_fp16<<<dim3(DD/128, BS/128), 256, 98304>>>(
        hp, fc2w, fc2_b, x1p, out, nullptr, nullptr, BS, DD, HID, 2);
}

// round 8
// speedup vs baseline: 7.6263x; 1.0217x over previous
#include <cuda_runtime.h>
#include <cuda_fp16.h>
#include <math.h>
#include <stdint.h>

#define BB 4
#define SS 2048
#define DD 768
#define HH 8
#define DHH 96
#define HID 3072
#define BS (BB*SS)          // 8192
#define SCALE_ATTN 0.1020620726159658f  // 1/sqrt(96)
#define NLOG_16 0.575646273248511f      // ln(10000)/16
#define EXP_NEG_C 0.5623413251903491f   // e^{-ln(10000)/16}

// ---------------- scratch (device globals; no allocation) ----------------
__device__ __half g_xn  [(size_t)BS * DD];        // LN1 out (fp16)
__device__ __half g_qkv [(size_t)BS * 3 * DD];    // qkv fp16 (rope fused in GEMM)
__device__ __half g_attn[(size_t)BS * DD];        // attention out fp16
__device__ float  g_x1  [(size_t)BS * DD];        // src + proj(attn), fp32 trunk
__device__ __half g_y   [(size_t)BS * DD];        // LN2 out fp16
__device__ __half g_h   [(size_t)BS * HID];       // fc1+gelu out fp16
// fp16 weights, SAME layout as fp32 originals: W[K, N]
__device__ __half g_qkvw16[(size_t)DD * (3*DD)];
__device__ __half g_projw16[(size_t)DD * DD];
__device__ __half g_fc1w16 [(size_t)DD * HID];
__device__ __half g_fc2w16 [(size_t)HID * DD];

// ---------------- helpers ---------------------------------------------------
__device__ __forceinline__ void cp_async16(uint32_t dst, const void* src) {
    asm volatile("cp.async.cg.shared.global [%0], [%1], 16;" :: "r"(dst), "l"(src));
}
__device__ __forceinline__ void cp_commit() { asm volatile("cp.async.commit_group;" ::: "memory"); }
__device__ __forceinline__ uint32_t smem_u32(const void* p) {
    uint32_t a;
    asm("{ .reg .u64 t; cvta.to.shared.u64 t, %1; cvt.u32.u64 %0, t; }" : "=r"(a) : "l"(p));
    return a;
}
__device__ __forceinline__ void ldm_x4(uint32_t* r, uint32_t addr) {
    asm volatile("ldmatrix.sync.aligned.m8n8.x4.shared.b16 {%0,%1,%2,%3}, [%4];"
        : "=r"(r[0]), "=r"(r[1]), "=r"(r[2]), "=r"(r[3]) : "r"(addr));
}
__device__ __forceinline__ void ldm_x4t(uint32_t* r, uint32_t addr) {
    asm volatile("ldmatrix.sync.aligned.m8n8.x4.trans.shared.b16 {%0,%1,%2,%3}, [%4];"
        : "=r"(r[0]), "=r"(r[1]), "=r"(r[2]), "=r"(r[3]) : "r"(addr));
}
__device__ __forceinline__ void mma16816(float* c, const uint32_t* a, const uint32_t* b) {
    asm volatile(
        "mma.sync.aligned.m16n8k16.row.col.f32.f16.f16.f32 "
        "{%0,%1,%2,%3}, {%4,%5,%6,%7}, {%8,%9}, {%0,%1,%2,%3};"
        : "+f"(c[0]), "+f"(c[1]), "+f"(c[2]), "+f"(c[3])
        : "r"(a[0]), "r"(a[1]), "r"(a[2]), "r"(a[3]), "r"(b[0]), "r"(b[1]));
}
__device__ __forceinline__ float gelu_fast(float x) {
    float z = 0.7978845608028654f * (x + 0.044715f * x * x * x);
    float t;
    asm("tanh.approx.f32 %0, %1;" : "=f"(t) : "f"(z));
    return 0.5f * x * (1.0f + t);
}

// ---------------- fused weight convert fp32 -> fp16 (no transpose) ----------
#define NW1 (DD*(3*DD)/4)
#define NW2 (DD*DD/4)
#define NW3 (DD*HID/4)
#define NW4 (HID*DD/4)
__global__ __launch_bounds__(256) void convert_w(const float* __restrict__ w1,
                                                 const float* __restrict__ w2,
                                                 const float* __restrict__ w3,
                                                 const float* __restrict__ w4) {
    int i = blockIdx.x * blockDim.x + threadIdx.x;
    const float* src; __half* dst; int off;
    if (i < NW1)                        { src = w1; dst = g_qkvw16;  off = i; }
    else if (i < NW1 + NW2)             { src = w2; dst = g_projw16; off = i - NW1; }
    else if (i < NW1 + NW2 + NW3)       { src = w3; dst = g_fc1w16;  off = i - NW1 - NW2; }
    else                                { src = w4; dst = g_fc2w16;  off = i - NW1 - NW2 - NW3; }
    float4 v = ((const float4*)src)[off];
    __half2 h0 = __floats2half2_rn(v.x, v.y);
    __half2 h1 = __floats2half2_rn(v.z, v.w);
    ((__half2*)dst)[off * 2]     = h0;
    ((__half2*)dst)[off * 2 + 1] = h1;
}

// ---------------- LayerNorm: one block per row, out fp16 --------------------
__global__ __launch_bounds__(256) void ln_kernel(const float* __restrict__ x,
                                                 const float* __restrict__ g,
                                                 const float* __restrict__ b,
                                                 __half* __restrict__ out) {
    int row = blockIdx.x;
    int t = threadIdx.x;
    const float* xr = x + (size_t)row * DD;
    float v0 = xr[t], v1 = xr[t + 256], v2 = xr[t + 512];
    float s  = v0 + v1 + v2;
    float ss = v0*v0 + v1*v1 + v2*v2;
    #pragma unroll
    for (int o = 16; o > 0; o >>= 1) {
        s  += __shfl_xor_sync(0xffffffffu, s,  o);
        ss += __shfl_xor_sync(0xffffffffu, ss, o);
    }
    __shared__ float rs[8], rss[8];
    if ((t & 31) == 0) { rs[t >> 5] = s; rss[t >> 5] = ss; }
    __syncthreads();
    float S1 = 0.f, S2 = 0.f;
    #pragma unroll
    for (int i = 0; i < 8; i++) { S1 += rs[i]; S2 += rss[i]; }
    float mean = S1 * (1.0f / DD);
    float var  = S2 * (1.0f / DD) - mean * mean;
    float rstd = rsqrtf(var + 1e-6f);
    __half* orow = out + (size_t)row * DD;
    orow[t      ] = __float2half_rn((v0 - mean) * rstd * g[t      ] + b[t      ]);
    orow[t + 256] = __float2half_rn((v1 - mean) * rstd * g[t + 256] + b[t + 256]);
    orow[t + 512] = __float2half_rn((v2 - mean) * rstd * g[t + 512] + b[t + 512]);
}

// ---------------- fp16 mma GEMM, B row-major [K,N] via ldmatrix.trans -------
// modes: 0 plain fp16; 1 GELU fp16; 2 +res fp32; 3 fused RoPE (QKV)
__global__ __launch_bounds__(256, 2) void gemm_fp16(const __half* __restrict__ A,
                                                    const __half* __restrict__ W,
                                                    const float* __restrict__ bias,
                                                    const float* __restrict__ res,
                                                    float* __restrict__ Cf,
                                                    __half* __restrict__ Ch,
                                                    const float* __restrict__ coords,
                                                    int M, int N, int K, int mode) {
    extern __shared__ char smem[];
    uint32_t sbase = smem_u32(smem);
    const int tid = threadIdx.x, lane = tid & 31, w = tid >> 5;
    const int m0 = blockIdx.y * 128, n0 = blockIdx.x * 128;

    const int ar = tid >> 1, ac = (tid & 1) * 4;
    const __half* aP = A + (size_t)(m0 + ar) * K + ac * 8;
    uint32_t aoff[4];
    #pragma unroll
    for (int j = 0; j < 4; j++)
        aoff[j] = (uint32_t)ar * 128u + (uint32_t)(((ac + j) ^ (ar & 7)) << 4);
    const int br = tid >> 2, bc = (tid & 3) * 4;
    const __half* bP = W + (size_t)br * N + n0 + bc * 8;
    uint32_t boff[4];
    #pragma unroll
    for (int j = 0; j < 4; j++) {
        int c = bc + j;
        boff[j] = (uint32_t)br * 256u + (uint32_t)(((c & 8) | ((c ^ br) & 7)) << 4);
    }

    const int NC = K / 64;

    float acc[2][8][4];
    #pragma unroll
    for (int mt = 0; mt < 2; mt++)
        #pragma unroll
        for (int nt = 0; nt < 8; nt++)
            #pragma unroll
            for (int i = 0; i < 4; i++) acc[mt][nt][i] = 0.f;

    const int L = lane & 7, gb = (lane >> 3) & 1, gh = lane >> 4;
    const int wm = (w >> 1) * 32, wn = (w & 1) * 64;
    uint32_t aRow[2];
    #pragma unroll
    for (int mt = 0; mt < 2; mt++) aRow[mt] = (uint32_t)(wm + mt * 16 + gb * 8 + L) * 128u;

    #pragma unroll
    for (int pre = 0; pre < 2; pre++) {
        if (pre < NC) {
            uint32_t sa = sbase + (uint32_t)pre * 32768u;
            uint32_t sb = sa + 16384;
            const __half* ap = aP + (size_t)pre * 64;
            const __half* bp = bP + (size_t)pre * 64 * N;
            #pragma unroll
            for (int j = 0; j < 4; j++) {
                cp_async16(sa + aoff[j], ap + j * 8);
                cp_async16(sb + boff[j], bp + j * 8);
            }
            cp_commit();
        }
    }

    for (int ch = 0; ch < NC; ch++) {
        if (ch < NC - 1) { asm volatile("cp.async.wait_group 1;" ::: "memory"); }
        else             { asm volatile("cp.async.wait_group 0;" ::: "memory"); }
        __syncthreads();

        if (ch + 2 < NC) {
            uint32_t na = sbase + (uint32_t)((ch + 2) % 3) * 32768u;
            uint32_t nb = na + 16384;
            const __half* ap = aP + (size_t)(ch + 2) * 64;
            const __half* bp = bP + (size_t)(ch + 2) * 64 * N;
            #pragma unroll
            for (int j = 0; j < 4; j++) {
                cp_async16(na + aoff[j], ap + j * 8);
                cp_async16(nb + boff[j], bp + j * 8);
            }
            cp_commit();
        }

        uint32_t stA = sbase + (uint32_t)(ch % 3) * 32768u;
        uint32_t stB = stA + 16384;

        #pragma unroll
        for (int ks = 0; ks < 4; ks++) {
            uint32_t af[2][4];
            #pragma unroll
            for (int mt = 0; mt < 2; mt++)
                ldm_x4(af[mt], stA + aRow[mt] + ((uint32_t)((2 * ks + gh) ^ L) << 4));
            int krow = ks * 16 + L + gb * 8;
            uint32_t rb = stB + (uint32_t)krow * 256u;
            uint32_t bf[4][4];
            #pragma unroll
            for (int p = 0; p < 4; p++) {
                int c = (wn >> 3) + 2 * p + gh;
                ldm_x4t(bf[p], rb + ((uint32_t)((c & 8) | ((c ^ L) & 7)) << 4));
            }
            #pragma unroll
            for (int mt = 0; mt < 2; mt++)
                #pragma unroll
                for (int p = 0; p < 4; p++) {
                    mma16816(acc[mt][2 * p],     af[mt], bf[p]);
                    mma16816(acc[mt][2 * p + 1], af[mt], bf[p] + 2);
                }
        }
    }

    // ---------------- epilogue ----------------
    const int lane4 = lane >> 2, u = lane & 3;
    if (mode == 3) {
        #pragma unroll
        for (int mt = 0; mt < 2; mt++) {
            #pragma unroll
            for (int hf = 0; hf < 2; hf++) {
                int m = m0 + wm + mt * 16 + lane4 + hf * 8;
                const float* cr = coords + (size_t)m * 3;
                __half* crow = Ch + (size_t)m * N;
                #pragma unroll
                for (int bi = 0; bi < 2; bi++) {
                    int colblk = n0 + wn + bi * 32;
                    int part = colblk / DD;          // 0=q,1=k,2=v
                    if (part == 2) {
                        #pragma unroll
                        for (int pp = 0; pp < 4; pp++) {
                            int nt = bi * 4 + pp;
                            int n = n0 + wn + nt * 8 + 2 * u;
                            float c0 = acc[mt][nt][hf * 2    ] + bias[n];
                            float c1 = acc[mt][nt][hf * 2 + 1] + bias[n + 1];
                            *(__half2*)(crow + n) = __floats2half2_rn(c0, c1);
                        }
                    } else {
                        int axis = (colblk % DHH) >> 5;
                        float coord = cr[axis];
                        float sc = (part == 0) ? SCALE_ATTN : 1.0f;
                        #pragma unroll
                        for (int pp = 0; pp < 2; pp++) {
                            int nt1 = bi * 4 + pp, nt2 = nt1 + 2;
                            int n1 = n0 + wn + nt1 * 8 + 2 * u;
                            int n2 = n1 + 16;
                            int j0 = pp * 8 + 2 * u;
                            float f0 = __expf((float)j0 * -NLOG_16);
                            float ang0 = coord * f0;
                            float ang1 = ang0 * EXP_NEG_C;   // chained inv_freq
                            float sn0, cs0, sn1, cs1;
                            __sincosf(ang0, &sn0, &cs0);
                            __sincosf(ang1, &sn1, &cs1);
                            float x10 = acc[mt][nt1][hf * 2    ] + bias[n1];
                            float x11 = acc[mt][nt1][hf * 2 + 1] + bias[n1 + 1];
                            float x20 = acc[mt][nt2][hf * 2    ] + bias[n2];
                            float x21 = acc[mt][nt2][hf * 2 + 1] + bias[n2 + 1];
                            *(__half2*)(crow + n1) = __floats2half2_rn(
                                sc * (x10 * cs0 - x20 * sn0), sc * (x11 * cs1 - x21 * sn1));
                            *(__half2*)(crow + n2) = __floats2half2_rn(
                                sc * (x10 * sn0 + x20 * cs0), sc * (x11 * sn1 + x21 * cs1));
                        }
                    }
                }
            }
        }
    } else {
        #pragma unroll
        for (int mt = 0; mt < 2; mt++) {
            #pragma unroll
            for (int hf = 0; hf < 2; hf++) {
                int m = m0 + wm + mt * 16 + lane4 + hf * 8;
                #pragma unroll
                for (int nt = 0; nt < 8; nt++) {
                    int n = n0 + wn + nt * 8 + 2 * u;
                    float c0 = acc[mt][nt][hf * 2    ] + bias[n];
                    float c1 = acc[mt][nt][hf * 2 + 1] + bias[n + 1];
                    if (mode == 2) {
                        const float* rrow = res + (size_t)m * N;
                        Cf[(size_t)m * N + n]     = c0 + rrow[n];
                        Cf[(size_t)m * N + n + 1] = c1 + rrow[n + 1];
                    } else {
                        if (mode == 1) {
                            c0 = gelu_fast(c0);
                            c1 = gelu_fast(c1);
                        }
                        *(__half2*)(Ch + (size_t)m * N + n) = __floats2half2_rn(c0, c1);
                    }
                }
            }
        }
    }
}

// ---------------- fp16 tensor-core causal flash attention -------------------
// 64 q-rows/block, 128 threads, kv tiles of 64, double-buffered K/V.
// qt reversed so longest CTAs schedule first (LPT packing).
__global__ __launch_bounds__(128) void attn_fp16() {
    extern __shared__ char sm[];
    const uint32_t base = smem_u32(sm);
    const int t = threadIdx.x, lane = t & 31, w = t >> 5;
    const int L = lane & 7, gb = (lane >> 3) & 1, gh = lane >> 4;
    const int lane4 = lane >> 2, u = lane & 3;
    const int qt = gridDim.x - 1 - blockIdx.x;      // longest-first
    const int bh = blockIdx.y;
    const int b = bh >> 3, h = bh & 7;
    const __half* qkv = g_qkv + (size_t)b * SS * (3 * DD);

    uint32_t soff[6]; int rows[6], cks[6];
    #pragma unroll
    for (int it = 0; it < 6; it++) {
        int idx = t + 128 * it;
        int row = idx / 12, c = idx % 12;
        rows[it] = row; cks[it] = c;
        soff[it] = (uint32_t)row * 256u + ((uint32_t)((c & 8) | ((c ^ row) & 7)) << 4);
    }

    // ---- stage Q into K0, extract fragments
    #pragma unroll
    for (int it = 0; it < 6; it++)
        cp_async16(base + soff[it], qkv + (size_t)(qt * 64 + rows[it]) * (3 * DD) + h * DHH + cks[it] * 8);
    cp_commit();
    asm volatile("cp.async.wait_group 0;" ::: "memory");
    __syncthreads();

    uint32_t qa[6][4];
    const uint32_t qRow = (uint32_t)(w * 16 + gb * 8 + L) * 256u;
    #pragma unroll
    for (int ks = 0; ks < 6; ks++) {
        int c = 2 * ks + gh;
        ldm_x4(qa[ks], base + qRow + ((uint32_t)((c & 8) | ((c ^ L) & 7)) << 4));
    }
    __syncthreads();

    float oacc[12][4];
    #pragma unroll
    for (int nt = 0; nt < 12; nt++)
        #pragma unroll
        for (int i = 0; i < 4; i++) oacc[nt][i] = 0.f;
    float m0 = -INFINITY, m1 = -INFINITY, l0 = 0.f, l1 = 0.f;

    uint32_t kRow[4];
    #pragma unroll
    for (int p = 0; p < 4; p++) kRow[p] = (uint32_t)(p * 16 + gh * 8 + L) * 256u;

    #pragma unroll
    for (int it = 0; it < 6; it++) {
        const __half* kp = qkv + (size_t)rows[it] * (3 * DD) + DD + h * DHH + cks[it] * 8;
        cp_async16(base + soff[it], kp);
        cp_async16(base + 32768u + soff[it], kp + DD);
    }
    cp_commit();

    for (int kt = 0; kt <= qt; kt++) {
        uint32_t buf = (uint32_t)(kt & 1) * 16384u;
        if (kt < qt) {
            uint32_t nbuf = (uint32_t)((kt + 1) & 1) * 16384u;
            #pragma unroll
            for (int it = 0; it < 6; it++) {
                const __half* kp = qkv + (size_t)((kt + 1) * 64 + rows[it]) * (3 * DD) + DD + h * DHH + cks[it] * 8;
                cp_async16(base + nbuf + soff[it], kp);
                cp_async16(base + 32768u + nbuf + soff[it], kp + DD);
            }
            cp_commit();
            asm volatile("cp.async.wait_group 1;" ::: "memory");
        } else {
            asm volatile("cp.async.wait_group 0;" ::: "memory");
        }
        __syncthreads();

        const uint32_t kb = base + buf;
        const uint32_t vb = base + 32768u + buf;

        float sfr[8][4];
        #pragma unroll
        for (int nt = 0; nt < 8; nt++)
            #pragma unroll
            for (int i = 0; i < 4; i++) sfr[nt][i] = 0.f;
        #pragma unroll
        for (int ks = 0; ks < 6; ks++) {
            int c = 2 * ks + gb;
            uint32_t coff = (uint32_t)((c & 8) | ((c ^ L) & 7)) << 4;
            #pragma unroll
            for (int p = 0; p < 4; p++) {
                uint32_t bf[4];
                ldm_x4(bf, kb + kRow[p] + coff);
                mma16816(sfr[2 * p],     qa[ks], bf);
                mma16816(sfr[2 * p + 1], qa[ks], bf + 2);
            }
        }
        if (kt == qt) {
            int r0 = w * 16 + lane4, r1 = r0 + 8;
            #pragma unroll
            for (int nt = 0; nt < 8; nt++) {
                int ca = nt * 8 + 2 * u, cbn = ca + 1;
                if (ca  > r0) sfr[nt][0] = -1e30f;
                if (cbn > r0) sfr[nt][1] = -1e30f;
                if (ca  > r1) sfr[nt][2] = -1e30f;
                if (cbn > r1) sfr[nt][3] = -1e30f;
            }
        }
        float mx0 = -INFINITY, mx1 = -INFINITY;
        #pragma unroll
        for (int nt = 0; nt < 8; nt++) {
            mx0 = fmaxf(mx0, fmaxf(sfr[nt][0], sfr[nt][1]));
            mx1 = fmaxf(mx1, fmaxf(sfr[nt][2], sfr[nt][3]));
        }
        mx0 = fmaxf(mx0, __shfl_xor_sync(0xffffffffu, mx0, 1));
        mx0 = fmaxf(mx0, __shfl_xor_sync(0xffffffffu, mx0, 2));
        mx1 = fmaxf(mx1, __shfl_xor_sync(0xffffffffu, mx1, 1));
        mx1 = fmaxf(mx1, __shfl_xor_sync(0xffffffffu, mx1, 2));
        float mn0 = fmaxf(m0, mx0), mn1 = fmaxf(m1, mx1);
        float al0 = __expf(m0 - mn0), al1 = __expf(m1 - mn1);
        m0 = mn0; m1 = mn1;
        l0 *= al0; l1 *= al1;
        #pragma unroll
        for (int nt = 0; nt < 12; nt++) {
            oacc[nt][0] *= al0; oacc[nt][1] *= al0;
            oacc[nt][2] *= al1; oacc[nt][3] *= al1;
        }
        #pragma unroll
        for (int nt = 0; nt < 8; nt++) {
            float p0 = __expf(sfr[nt][0] - mn0), p1 = __expf(sfr[nt][1] - mn0);
            float p2 = __expf(sfr[nt][2] - mn1), p3 = __expf(sfr[nt][3] - mn1);
            l0 += p0 + p1; l1 += p2 + p3;
            sfr[nt][0] = p0; sfr[nt][1] = p1; sfr[nt][2] = p2; sfr[nt][3] = p3;
        }
        #pragma unroll
        for (int j = 0; j < 4; j++) {
            uint32_t a[4];
            __half2 h0 = __floats2half2_rn(sfr[2*j][0],     sfr[2*j][1]);
            __half2 h1 = __floats2half2_rn(sfr[2*j][2],     sfr[2*j][3]);
            __half2 h2 = __floats2half2_rn(sfr[2*j + 1][0], sfr[2*j + 1][1]);
            __half2 h3 = __floats2half2_rn(sfr[2*j + 1][2], sfr[2*j + 1][3]);
            a[0] = *(uint32_t*)&h0; a[1] = *(uint32_t*)&h1;
            a[2] = *(uint32_t*)&h2; a[3] = *(uint32_t*)&h3;
            uint32_t rv = vb + (uint32_t)(j * 16 + L + gb * 8) * 256u;
            #pragma unroll
            for (int p = 0; p < 6; p++) {
                int c = 2 * p + gh;
                uint32_t bf[4];
                ldm_x4t(bf, rv + ((uint32_t)((c & 8) | ((c ^ L) & 7)) << 4));
                mma16816(oacc[2 * p],     a, bf);
                mma16816(oacc[2 * p + 1], a, bf + 2);
            }
        }
        __syncthreads();
    }

    l0 += __shfl_xor_sync(0xffffffffu, l0, 1);
    l0 += __shfl_xor_sync(0xffffffffu, l0, 2);
    l1 += __shfl_xor_sync(0xffffffffu, l1, 1);
    l1 += __shfl_xor_sync(0xffffffffu, l1, 2);
    float i0 = 1.0f / l0, i1 = 1.0f / l1;
    int gr0 = qt * 64 + w * 16 + lane4, gr1 = gr0 + 8;
    __half* o0 = g_attn + (size_t)(b * SS + gr0) * DD + h * DHH;
    __half* o1 = g_attn + (size_t)(b * SS + gr1) * DD + h * DHH;
    #pragma unroll
    for (int nt = 0; nt < 12; nt++) {
        int c = nt * 8 + 2 * u;
        __half2 a0 = __floats2half2_rn(oacc[nt][0] * i0, oacc[nt][1] * i0);
        __half2 a1 = __floats2half2_rn(oacc[nt][2] * i1, oacc[nt][3] * i1);
        *(__half2*)(o0 + c) = a0;
        *(__half2*)(o1 + c) = a1;
    }
}

// ---------------- launch ----------------------------------------------------
extern "C" void kernel_launch(void* const* d_in, const int* in_sizes, int n_in,
                              void* d_out, int out_size) {
    const float* src     = (const float*)d_in[0];
    const float* coords  = (const float*)d_in[1];
    const float* norm1_g = (const float*)d_in[3];
    const float* norm1_b = (const float*)d_in[4];
    const float* qkv_w   = (const float*)d_in[5];
    const float* qkv_b   = (const float*)d_in[6];
    const float* proj_w  = (const float*)d_in[7];
    const float* proj_b  = (const float*)d_in[8];
    const float* norm2_g = (const float*)d_in[9];
    const float* norm2_b = (const float*)d_in[10];
    const float* fc1_w   = (const float*)d_in[11];
    const float* fc1_b   = (const float*)d_in[12];
    const float* fc2_w   = (const float*)d_in[13];
    const float* fc2_b   = (const float*)d_in[14];
    float* out = (float*)d_out;

    __half *xn, *qkvp, *attnp, *yp, *hp;
    __half *qkvw, *projw, *fc1w, *fc2w;
    float *x1p;
    cudaGetSymbolAddress((void**)&xn,    g_xn);
    cudaGetSymbolAddress((void**)&qkvp,  g_qkv);
    cudaGetSymbolAddress((void**)&attnp, g_attn);
    cudaGetSymbolAddress((void**)&x1p,   g_x1);
    cudaGetSymbolAddress((void**)&yp,    g_y);
    cudaGetSymbolAddress((void**)&hp,    g_h);
    cudaGetSymbolAddress((void**)&qkvw,  g_qkvw16);
    cudaGetSymbolAddress((void**)&projw, g_projw16);
    cudaGetSymbolAddress((void**)&fc1w,  g_fc1w16);
    cudaGetSymbolAddress((void**)&fc2w,  g_fc2w16);

    static bool attr_set = false;
    if (!attr_set) {
        cudaFuncSetAttribute(gemm_fp16, cudaFuncAttributeMaxDynamicSharedMemorySize, 98304);
        cudaFuncSetAttribute(attn_fp16, cudaFuncAttributeMaxDynamicSharedMemorySize, 65536);
        attr_set = true;
    }

    convert_w<<<(NW1 + NW2 + NW3 + NW4) / 256, 256>>>(qkv_w, proj_w, fc1_w, fc2_w);
    ln_kernel<<<BS, 256>>>(src, norm1_g, norm1_b, xn);
    gemm_fp16<<<dim3((3*DD)/128, BS/128), 256, 98304>>>(
        xn, qkvw, qkv_b, nullptr, nullptr, qkvp, coords, BS, 3*DD, DD, 3);
    attn_fp16<<<dim3(SS / 64, BB * HH), 128, 65536>>>();
    gemm_fp16<<<dim3(DD/128, BS/128), 256, 98304>>>(
        attnp, projw, proj_b, src, x1p, nullptr, nullptr, BS, DD, DD, 2);
    ln_kernel<<<BS, 256>>>(x1p, norm2_g, norm2_b, yp);
    gemm_fp16<<<dim3(HID/128, BS/128), 256, 98304>>>(
        yp, fc1w, fc1_b, nullptr, nullptr, hp, nullptr, BS, HID, DD, 1);
    gemm_fp16<<<dim3(DD/128, BS/128), 256, 98304>>>(
        hp, fc2w, fc2_b, x1p, out, nullptr, nullptr, BS, DD, HID, 2);
}